// round 1
// baseline (speedup 1.0000x reference)
#include <cuda_runtime.h>

#define Bb 4
#define Ss 2048
#define DM 1024
#define Hh 16
#define Dh 64
#define NEG_BIG 1e10f
#define KT_STRIDE 68

// Scratch for projected Q/K/V in [B, H, S, 64] layout (allocation-free rule:
// __device__ globals only).
__device__ float g_qw[Bb * Hh * Ss * Dh];
__device__ float g_kw[Bb * Hh * Ss * Dh];
__device__ float g_vw[Bb * Hh * Ss * Dh];

// ---------------------------------------------------------------------------
// Projection GEMM: X[8192,1024] @ W[1024,1024], z selects q/k/v.
// 128x128 tile, BK=8, 256 threads, 8x8 per thread.
// Epilogue scatters into [B,H,S,64].
// ---------------------------------------------------------------------------
__global__ __launch_bounds__(256)
void proj_kernel(const float* __restrict__ qin, const float* __restrict__ kin,
                 const float* __restrict__ vin,
                 const float* __restrict__ Wq, const float* __restrict__ Wk,
                 const float* __restrict__ Wv)
{
    const int z = blockIdx.z;
    const float* X = (z == 0) ? qin : (z == 1) ? kin : vin;
    const float* W = (z == 0) ? Wq : (z == 1) ? Wk : Wv;
    float* O = (z == 0) ? g_qw : (z == 1) ? g_kw : g_vw;

    __shared__ float As[8][128];   // transposed A tile
    __shared__ float Bs[8][128];

    const int tid = threadIdx.x;
    const int m0 = blockIdx.y * 128;
    const int n0 = blockIdx.x * 128;

    const int a_row = tid >> 1;
    const int a_col = (tid & 1) << 2;
    const int b_row = tid >> 5;
    const int b_col = (tid & 31) << 2;

    const int ty = tid >> 4;   // 0..15
    const int tx = tid & 15;   // 0..15

    float acc[8][8];
#pragma unroll
    for (int i = 0; i < 8; i++)
#pragma unroll
        for (int j = 0; j < 8; j++) acc[i][j] = 0.f;

    for (int k0 = 0; k0 < DM; k0 += 8) {
        float4 av = *(const float4*)&X[(m0 + a_row) * DM + k0 + a_col];
        As[a_col + 0][a_row] = av.x;
        As[a_col + 1][a_row] = av.y;
        As[a_col + 2][a_row] = av.z;
        As[a_col + 3][a_row] = av.w;
        *(float4*)&Bs[b_row][b_col] =
            *(const float4*)&W[(k0 + b_row) * DM + n0 + b_col];
        __syncthreads();
#pragma unroll
        for (int kk = 0; kk < 8; kk++) {
            float a[8], b[8];
            *(float4*)&a[0] = *(float4*)&As[kk][ty * 8];
            *(float4*)&a[4] = *(float4*)&As[kk][ty * 8 + 4];
            *(float4*)&b[0] = *(float4*)&Bs[kk][tx * 8];
            *(float4*)&b[4] = *(float4*)&Bs[kk][tx * 8 + 4];
#pragma unroll
            for (int i = 0; i < 8; i++)
#pragma unroll
                for (int j = 0; j < 8; j++)
                    acc[i][j] += a[i] * b[j];
        }
        __syncthreads();
    }

    // Epilogue: n = h*64 + d, write into [B,H,S,64].
    const int n_base = n0 + tx * 8;
    const int h = n_base >> 6;
    const int d0 = n_base & 63;
#pragma unroll
    for (int i = 0; i < 8; i++) {
        int m = m0 + ty * 8 + i;
        int b_ = m >> 11;
        int s = m & 2047;
        float* op = &O[(((b_ * Hh + h) * Ss) + s) * Dh + d0];
        *(float4*)&op[0] = make_float4(acc[i][0], acc[i][1], acc[i][2], acc[i][3]);
        *(float4*)&op[4] = make_float4(acc[i][4], acc[i][5], acc[i][6], acc[i][7]);
    }
}

// ---------------------------------------------------------------------------
// Causal flash attention: one CTA per (64 q-rows, b*h). 64x64 KV tiles,
// online softmax, fp32 throughout.
// ---------------------------------------------------------------------------
__global__ __launch_bounds__(256)
void fa_kernel(const float* __restrict__ vmask, const float* __restrict__ qmask,
               float* __restrict__ out)
{
    extern __shared__ float sm[];
    float* Qs  = sm;                       // [64][64] row-major (q-row, d)
    float* Kt  = Qs + 64 * 64;             // [64][KT_STRIDE] d-major (d, kv)
    float* Vs  = Kt + 64 * KT_STRIDE;      // [64][64] row-major (kv, d)
    float* Ps  = Vs + 64 * 64;             // [64][64] (q-row, kv)
    float* vmS = Ps + 64 * 64;             // [64]

    const int qt = blockIdx.x;
    const int bh = blockIdx.y;
    const int b_ = bh >> 4;
    const int h  = bh & 15;
    const int tid = threadIdx.x;
    const int ty = tid >> 4;        // 0..15 (q-row groups of 4)
    const int tx = tid & 15;        // 0..15 (col groups of 4)
    const int lr = tid >> 4;        // loader row base
    const int lc = (tid & 15) << 2; // loader col (float4)

    // Load Q tile
    const float* Qg = &g_qw[(bh * Ss + qt * 64) * Dh];
#pragma unroll
    for (int i = 0; i < 4; i++) {
        int r = lr + i * 16;
        *(float4*)&Qs[r * 64 + lc] = *(const float4*)&Qg[r * 64 + lc];
    }

    const float NEG_INF = -__int_as_float(0x7f800000);
    float m_i[4], l_i[4], acc[4][4];
#pragma unroll
    for (int i = 0; i < 4; i++) {
        m_i[i] = NEG_INF;
        l_i[i] = 0.f;
#pragma unroll
        for (int j = 0; j < 4; j++) acc[i][j] = 0.f;
    }

    const int qbase = qt * 64 + ty * 4;

    for (int jt = 0; jt <= qt; jt++) {
        __syncthreads();  // prev iter's PV reads of Vs done; Qs visible (iter 0)

        // Load K (transposed to d-major), V, v_mask for this KV tile
        const float* Kg = &g_kw[(bh * Ss + jt * 64) * Dh];
        const float* Vg = &g_vw[(bh * Ss + jt * 64) * Dh];
#pragma unroll
        for (int i = 0; i < 4; i++) {
            int r = lr + i * 16;  // kv row
            float4 kv = *(const float4*)&Kg[r * 64 + lc];
            Kt[(lc + 0) * KT_STRIDE + r] = kv.x;
            Kt[(lc + 1) * KT_STRIDE + r] = kv.y;
            Kt[(lc + 2) * KT_STRIDE + r] = kv.z;
            Kt[(lc + 3) * KT_STRIDE + r] = kv.w;
            *(float4*)&Vs[r * 64 + lc] = *(const float4*)&Vg[r * 64 + lc];
        }
        if (tid < 64) vmS[tid] = vmask[b_ * Ss + jt * 64 + tid];
        __syncthreads();

        // S = Q @ K^T (4x4 per thread)
        float s[4][4];
#pragma unroll
        for (int i = 0; i < 4; i++)
#pragma unroll
            for (int j = 0; j < 4; j++) s[i][j] = 0.f;

        for (int kk = 0; kk < 64; kk += 4) {
            float a[4][4];
#pragma unroll
            for (int i = 0; i < 4; i++) {
                float4 t = *(float4*)&Qs[(ty * 4 + i) * 64 + kk];
                a[i][0] = t.x; a[i][1] = t.y; a[i][2] = t.z; a[i][3] = t.w;
            }
#pragma unroll
            for (int kc = 0; kc < 4; kc++) {
                float4 bk = *(float4*)&Kt[(kk + kc) * KT_STRIDE + tx * 4];
#pragma unroll
                for (int i = 0; i < 4; i++) {
                    s[i][0] += a[i][kc] * bk.x;
                    s[i][1] += a[i][kc] * bk.y;
                    s[i][2] += a[i][kc] * bk.z;
                    s[i][3] += a[i][kc] * bk.w;
                }
            }
        }

        // scale + masks (exactly the reference's additive -1e10 terms)
        const int kbase = jt * 64 + tx * 4;
        const bool diag = (jt == qt);
        float vmv[4];
#pragma unroll
        for (int j = 0; j < 4; j++) vmv[j] = vmS[tx * 4 + j];
#pragma unroll
        for (int i = 0; i < 4; i++)
#pragma unroll
            for (int j = 0; j < 4; j++) {
                float val = s[i][j] * 0.125f - (1.f - vmv[j]) * NEG_BIG;
                if (diag && (kbase + j > qbase + i)) val -= NEG_BIG;
                s[i][j] = val;
            }

        // online softmax (row reductions over 16-lane groups)
#pragma unroll
        for (int i = 0; i < 4; i++) {
            float rm = fmaxf(fmaxf(s[i][0], s[i][1]), fmaxf(s[i][2], s[i][3]));
            rm = fmaxf(rm, __shfl_xor_sync(0xffffffffu, rm, 8, 16));
            rm = fmaxf(rm, __shfl_xor_sync(0xffffffffu, rm, 4, 16));
            rm = fmaxf(rm, __shfl_xor_sync(0xffffffffu, rm, 2, 16));
            rm = fmaxf(rm, __shfl_xor_sync(0xffffffffu, rm, 1, 16));
            float mnew = fmaxf(m_i[i], rm);
            float corr = __expf(m_i[i] - mnew);
            float rs = 0.f;
#pragma unroll
            for (int j = 0; j < 4; j++) {
                float p = __expf(s[i][j] - mnew);
                s[i][j] = p;
                rs += p;
            }
            rs += __shfl_xor_sync(0xffffffffu, rs, 8, 16);
            rs += __shfl_xor_sync(0xffffffffu, rs, 4, 16);
            rs += __shfl_xor_sync(0xffffffffu, rs, 2, 16);
            rs += __shfl_xor_sync(0xffffffffu, rs, 1, 16);
            l_i[i] = l_i[i] * corr + rs;
            m_i[i] = mnew;
#pragma unroll
            for (int j = 0; j < 4; j++) acc[i][j] *= corr;
            *(float4*)&Ps[(ty * 4 + i) * 64 + tx * 4] =
                make_float4(s[i][0], s[i][1], s[i][2], s[i][3]);
        }
        __syncthreads();

        // O += P @ V
        for (int kk = 0; kk < 64; kk += 4) {
            float p[4][4];
#pragma unroll
            for (int i = 0; i < 4; i++) {
                float4 t = *(float4*)&Ps[(ty * 4 + i) * 64 + kk];
                p[i][0] = t.x; p[i][1] = t.y; p[i][2] = t.z; p[i][3] = t.w;
            }
#pragma unroll
            for (int kc = 0; kc < 4; kc++) {
                float4 vv = *(float4*)&Vs[(kk + kc) * 64 + tx * 4];
#pragma unroll
                for (int i = 0; i < 4; i++) {
                    acc[i][0] += p[i][kc] * vv.x;
                    acc[i][1] += p[i][kc] * vv.y;
                    acc[i][2] += p[i][kc] * vv.z;
                    acc[i][3] += p[i][kc] * vv.w;
                }
            }
        }
    }

    // Epilogue: normalize, apply q_mask, write [B,S,1024]
#pragma unroll
    for (int i = 0; i < 4; i++) {
        int qrow = qt * 64 + ty * 4 + i;
        float scale = qmask[b_ * Ss + qrow] / l_i[i];
        *(float4*)&out[(b_ * Ss + qrow) * DM + h * 64 + tx * 4] =
            make_float4(acc[i][0] * scale, acc[i][1] * scale,
                        acc[i][2] * scale, acc[i][3] * scale);
    }
}

extern "C" void kernel_launch(void* const* d_in, const int* in_sizes, int n_in,
                              void* d_out, int out_size)
{
    const float* q     = (const float*)d_in[0];
    const float* k     = (const float*)d_in[1];
    const float* v     = (const float*)d_in[2];
    const float* vmask = (const float*)d_in[3];
    const float* qmask = (const float*)d_in[4];
    const float* Wq    = (const float*)d_in[5];
    const float* Wk    = (const float*)d_in[6];
    const float* Wv    = (const float*)d_in[7];
    float* out = (float*)d_out;

    dim3 pg(DM / 128, (Bb * Ss) / 128, 3);
    proj_kernel<<<pg, 256>>>(q, k, v, Wq, Wk, Wv);

    size_t smem = (size_t)(64 * 64 * 3 + 64 * KT_STRIDE + 64) * sizeof(float);
    cudaFuncSetAttribute(fa_kernel, cudaFuncAttributeMaxDynamicSharedMemorySize,
                         (int)smem);
    dim3 fg(Ss / 64, Bb * Hh);
    fa_kernel<<<fg, 256, smem>>>(vmask, qmask, out);
}

// round 3
// speedup vs baseline: 1.5642x; 1.5642x over previous
#include <cuda_runtime.h>
#include <cstdint>

#define Bb 4
#define Ss 2048
#define DM 1024
#define Hh 16
#define Dh 64
#define NEG_BIG 1e10f
#define KT_STRIDE 68

// Scratch (allocation-free rule: __device__ globals).
__device__ float g_qw[Bb * Hh * Ss * Dh];
__device__ float g_kw[Bb * Hh * Ss * Dh];
__device__ float g_vw[Bb * Hh * Ss * Dh];
__device__ float g_Wt[3 * DM * DM];          // W^T [N,K], tf32-formatted
__device__ float g_Xt[3 * Bb * Ss * DM];     // inputs, tf32-formatted

__device__ __forceinline__ uint32_t smem_u32(const void* p) {
    uint32_t a;
    asm("{ .reg .u64 t; cvta.to.shared.u64 t, %1; cvt.u32.u64 %0, t; }"
        : "=r"(a) : "l"(p));
    return a;
}
__device__ __forceinline__ uint32_t f2tf32(float f) {
    uint32_t r;
    asm("cvt.rna.tf32.f32 %0, %1;" : "=r"(r) : "f"(f));
    return r;
}
__device__ __forceinline__ void cp_async16(uint32_t dst, const void* src) {
    asm volatile("cp.async.cg.shared.global [%0], [%1], 16;"
                 :: "r"(dst), "l"(src) : "memory");
}
__device__ __forceinline__ void mma_tf32(float* d, const uint32_t* a,
                                         const uint32_t* b) {
    asm volatile(
        "mma.sync.aligned.m16n8k8.row.col.f32.tf32.tf32.f32 "
        "{%0,%1,%2,%3}, {%4,%5,%6,%7}, {%8,%9}, {%0,%1,%2,%3};"
        : "+f"(d[0]), "+f"(d[1]), "+f"(d[2]), "+f"(d[3])
        : "r"(a[0]), "r"(a[1]), "r"(a[2]), "r"(a[3]), "r"(b[0]), "r"(b[1]));
}

// ---------------------------------------------------------------------------
// Pre-pass 1: convert inputs to tf32-formatted fp32 in g_Xt.
// ---------------------------------------------------------------------------
__global__ __launch_bounds__(256)
void cvt_kernel(const float* __restrict__ q, const float* __restrict__ k,
                const float* __restrict__ v)
{
    const float* src = (blockIdx.y == 0) ? q : (blockIdx.y == 1) ? k : v;
    float* dst = g_Xt + (size_t)blockIdx.y * (Bb * Ss * DM);
    size_t i = ((size_t)blockIdx.x * 256 + threadIdx.x) * 4;
    float4 x = *(const float4*)&src[i];
    uint4 t = make_uint4(f2tf32(x.x), f2tf32(x.y), f2tf32(x.z), f2tf32(x.w));
    *(uint4*)&dst[i] = t;
}

// ---------------------------------------------------------------------------
// Pre-pass 2: Wt[n*DM + k] = tf32(W[k*DM + n])
// ---------------------------------------------------------------------------
__global__ __launch_bounds__(256)
void wt_kernel(const float* __restrict__ Wq, const float* __restrict__ Wk,
               const float* __restrict__ Wv)
{
    const float* W = (blockIdx.z == 0) ? Wq : (blockIdx.z == 1) ? Wk : Wv;
    float* Wt = g_Wt + (size_t)blockIdx.z * DM * DM;
    __shared__ float t[32][33];
    int x0 = blockIdx.x * 32, y0 = blockIdx.y * 32;
    int tx = threadIdx.x & 31, ty = threadIdx.x >> 5;  // 32 x 8
#pragma unroll
    for (int i = 0; i < 4; i++)
        t[ty + i * 8][tx] = W[(y0 + ty + i * 8) * DM + x0 + tx];
    __syncthreads();
#pragma unroll
    for (int i = 0; i < 4; i++)
        Wt[(x0 + ty + i * 8) * DM + y0 + tx] =
            __uint_as_float(f2tf32(t[tx][ty + i * 8]));
}

// ---------------------------------------------------------------------------
// Projection GEMM: mma.sync tf32. CTA 128x128, BK=16, 8 warps (2x4),
// warp tile 64x32. cp.async double-buffered smem, KP=20 pad (conflict-free).
// ---------------------------------------------------------------------------
#define BM 128
#define BN 128
#define BK 16
#define KP 20

__global__ __launch_bounds__(256, 2)
void proj_mma_kernel()
{
    __shared__ float As[2][BM * KP];
    __shared__ float Bs[2][BN * KP];

    const int z = blockIdx.z;
    const float* X  = g_Xt + (size_t)z * (Bb * Ss * DM);
    const float* Wt = g_Wt + (size_t)z * DM * DM;
    float* O = (z == 0) ? g_qw : (z == 1) ? g_kw : g_vw;

    const int m0 = blockIdx.y * BM;
    const int n0 = blockIdx.x * BN;
    const int tid = threadIdx.x;
    const int lane = tid & 31;
    const int warp = tid >> 5;
    const int wm = (warp >> 2) * 64;
    const int wn = (warp & 3) * 32;

    const int lr = tid >> 2;          // loader rows lr, lr+64
    const int lk = (tid & 3) * 4;     // loader k offset (float4)

    const uint32_t sA0 = smem_u32(&As[0][0]);
    const uint32_t sA1 = smem_u32(&As[1][0]);
    const uint32_t sB0 = smem_u32(&Bs[0][0]);
    const uint32_t sB1 = smem_u32(&Bs[1][0]);

    float acc[4][4][4];
#pragma unroll
    for (int i = 0; i < 4; i++)
#pragma unroll
        for (int j = 0; j < 4; j++)
#pragma unroll
            for (int c = 0; c < 4; c++) acc[i][j][c] = 0.f;

    auto issue = [&](int kt, int bsel) {
        const int k0 = kt * BK;
        const uint32_t dA = bsel ? sA1 : sA0;
        const uint32_t dB = bsel ? sB1 : sB0;
        cp_async16(dA + (uint32_t)(lr * KP + lk) * 4,
                   &X[(size_t)(m0 + lr) * DM + k0 + lk]);
        cp_async16(dA + (uint32_t)((lr + 64) * KP + lk) * 4,
                   &X[(size_t)(m0 + lr + 64) * DM + k0 + lk]);
        cp_async16(dB + (uint32_t)(lr * KP + lk) * 4,
                   &Wt[(size_t)(n0 + lr) * DM + k0 + lk]);
        cp_async16(dB + (uint32_t)((lr + 64) * KP + lk) * 4,
                   &Wt[(size_t)(n0 + lr + 64) * DM + k0 + lk]);
        asm volatile("cp.async.commit_group;" ::: "memory");
    };

    issue(0, 0);

    for (int kt = 0; kt < DM / BK; kt++) {
        const int b = kt & 1;
        asm volatile("cp.async.wait_group 0;" ::: "memory");
        __syncthreads();
        if (kt + 1 < DM / BK) issue(kt + 1, b ^ 1);

        const float* as = &As[b][0];
        const float* bs = &Bs[b][0];
#pragma unroll
        for (int ks = 0; ks < 2; ks++) {
            uint32_t a[4][4];
#pragma unroll
            for (int mf = 0; mf < 4; mf++) {
                const float* p =
                    &as[(wm + mf * 16 + (lane >> 2)) * KP + ks * 8 + (lane & 3)];
                a[mf][0] = __float_as_uint(p[0]);
                a[mf][1] = __float_as_uint(p[8 * KP]);
                a[mf][2] = __float_as_uint(p[4]);
                a[mf][3] = __float_as_uint(p[8 * KP + 4]);
            }
            uint32_t bb[4][2];
#pragma unroll
            for (int nf = 0; nf < 4; nf++) {
                const float* p =
                    &bs[(wn + nf * 8 + (lane >> 2)) * KP + ks * 8 + (lane & 3)];
                bb[nf][0] = __float_as_uint(p[0]);
                bb[nf][1] = __float_as_uint(p[4]);
            }
#pragma unroll
            for (int mf = 0; mf < 4; mf++)
#pragma unroll
                for (int nf = 0; nf < 4; nf++)
                    mma_tf32(acc[mf][nf], a[mf], bb[nf]);
        }
        __syncthreads();
    }

    // Epilogue: scatter into [B,H,S,64].
#pragma unroll
    for (int mf = 0; mf < 4; mf++) {
#pragma unroll
        for (int nf = 0; nf < 4; nf++) {
            int m = m0 + wm + mf * 16 + (lane >> 2);
            int n = n0 + wn + nf * 8 + 2 * (lane & 3);
            int b_ = m >> 11, s = m & 2047, h = n >> 6, d = n & 63;
            float* op = &O[((((size_t)b_ * Hh + h) * Ss) + s) * Dh + d];
            *(float2*)op = make_float2(acc[mf][nf][0], acc[mf][nf][1]);
            *(float2*)(op + 8 * Dh) = make_float2(acc[mf][nf][2], acc[mf][nf][3]);
        }
    }
}

// ---------------------------------------------------------------------------
// Causal flash attention (unchanged from R1).
// ---------------------------------------------------------------------------
__global__ __launch_bounds__(256)
void fa_kernel(const float* __restrict__ vmask, const float* __restrict__ qmask,
               float* __restrict__ out)
{
    extern __shared__ float sm[];
    float* Qs  = sm;
    float* Kt  = Qs + 64 * 64;
    float* Vs  = Kt + 64 * KT_STRIDE;
    float* Ps  = Vs + 64 * 64;
    float* vmS = Ps + 64 * 64;

    const int qt = blockIdx.x;
    const int bh = blockIdx.y;
    const int b_ = bh >> 4;
    const int h  = bh & 15;
    const int tid = threadIdx.x;
    const int ty = tid >> 4;
    const int tx = tid & 15;
    const int lr = tid >> 4;
    const int lc = (tid & 15) << 2;

    const float* Qg = &g_qw[(size_t)(bh * Ss + qt * 64) * Dh];
#pragma unroll
    for (int i = 0; i < 4; i++) {
        int r = lr + i * 16;
        *(float4*)&Qs[r * 64 + lc] = *(const float4*)&Qg[r * 64 + lc];
    }

    const float NEG_INF = -__int_as_float(0x7f800000);
    float m_i[4], l_i[4], acc[4][4];
#pragma unroll
    for (int i = 0; i < 4; i++) {
        m_i[i] = NEG_INF;
        l_i[i] = 0.f;
#pragma unroll
        for (int j = 0; j < 4; j++) acc[i][j] = 0.f;
    }

    const int qbase = qt * 64 + ty * 4;

    for (int jt = 0; jt <= qt; jt++) {
        __syncthreads();
        const float* Kg = &g_kw[(size_t)(bh * Ss + jt * 64) * Dh];
        const float* Vg = &g_vw[(size_t)(bh * Ss + jt * 64) * Dh];
#pragma unroll
        for (int i = 0; i < 4; i++) {
            int r = lr + i * 16;
            float4 kv = *(const float4*)&Kg[r * 64 + lc];
            Kt[(lc + 0) * KT_STRIDE + r] = kv.x;
            Kt[(lc + 1) * KT_STRIDE + r] = kv.y;
            Kt[(lc + 2) * KT_STRIDE + r] = kv.z;
            Kt[(lc + 3) * KT_STRIDE + r] = kv.w;
            *(float4*)&Vs[r * 64 + lc] = *(const float4*)&Vg[r * 64 + lc];
        }
        if (tid < 64) vmS[tid] = vmask[b_ * Ss + jt * 64 + tid];
        __syncthreads();

        float s[4][4];
#pragma unroll
        for (int i = 0; i < 4; i++)
#pragma unroll
            for (int j = 0; j < 4; j++) s[i][j] = 0.f;

        for (int kk = 0; kk < 64; kk += 4) {
            float a[4][4];
#pragma unroll
            for (int i = 0; i < 4; i++) {
                float4 t = *(float4*)&Qs[(ty * 4 + i) * 64 + kk];
                a[i][0] = t.x; a[i][1] = t.y; a[i][2] = t.z; a[i][3] = t.w;
            }
#pragma unroll
            for (int kc = 0; kc < 4; kc++) {
                float4 bk = *(float4*)&Kt[(kk + kc) * KT_STRIDE + tx * 4];
#pragma unroll
                for (int i = 0; i < 4; i++) {
                    s[i][0] += a[i][kc] * bk.x;
                    s[i][1] += a[i][kc] * bk.y;
                    s[i][2] += a[i][kc] * bk.z;
                    s[i][3] += a[i][kc] * bk.w;
                }
            }
        }

        const int kbase = jt * 64 + tx * 4;
        const bool diag = (jt == qt);
        float vmv[4];
#pragma unroll
        for (int j = 0; j < 4; j++) vmv[j] = vmS[tx * 4 + j];
#pragma unroll
        for (int i = 0; i < 4; i++)
#pragma unroll
            for (int j = 0; j < 4; j++) {
                float val = s[i][j] * 0.125f - (1.f - vmv[j]) * NEG_BIG;
                if (diag && (kbase + j > qbase + i)) val -= NEG_BIG;
                s[i][j] = val;
            }

#pragma unroll
        for (int i = 0; i < 4; i++) {
            float rm = fmaxf(fmaxf(s[i][0], s[i][1]), fmaxf(s[i][2], s[i][3]));
            rm = fmaxf(rm, __shfl_xor_sync(0xffffffffu, rm, 8, 16));
            rm = fmaxf(rm, __shfl_xor_sync(0xffffffffu, rm, 4, 16));
            rm = fmaxf(rm, __shfl_xor_sync(0xffffffffu, rm, 2, 16));
            rm = fmaxf(rm, __shfl_xor_sync(0xffffffffu, rm, 1, 16));
            float mnew = fmaxf(m_i[i], rm);
            float corr = __expf(m_i[i] - mnew);
            float rs = 0.f;
#pragma unroll
            for (int j = 0; j < 4; j++) {
                float p = __expf(s[i][j] - mnew);
                s[i][j] = p;
                rs += p;
            }
            rs += __shfl_xor_sync(0xffffffffu, rs, 8, 16);
            rs += __shfl_xor_sync(0xffffffffu, rs, 4, 16);
            rs += __shfl_xor_sync(0xffffffffu, rs, 2, 16);
            rs += __shfl_xor_sync(0xffffffffu, rs, 1, 16);
            l_i[i] = l_i[i] * corr + rs;
            m_i[i] = mnew;
#pragma unroll
            for (int j = 0; j < 4; j++) acc[i][j] *= corr;
            *(float4*)&Ps[(ty * 4 + i) * 64 + tx * 4] =
                make_float4(s[i][0], s[i][1], s[i][2], s[i][3]);
        }
        __syncthreads();

        for (int kk = 0; kk < 64; kk += 4) {
            float p[4][4];
#pragma unroll
            for (int i = 0; i < 4; i++) {
                float4 t = *(float4*)&Ps[(ty * 4 + i) * 64 + kk];
                p[i][0] = t.x; p[i][1] = t.y; p[i][2] = t.z; p[i][3] = t.w;
            }
#pragma unroll
            for (int kc = 0; kc < 4; kc++) {
                float4 vv = *(float4*)&Vs[(kk + kc) * 64 + tx * 4];
#pragma unroll
                for (int i = 0; i < 4; i++) {
                    acc[i][0] += p[i][kc] * vv.x;
                    acc[i][1] += p[i][kc] * vv.y;
                    acc[i][2] += p[i][kc] * vv.z;
                    acc[i][3] += p[i][kc] * vv.w;
                }
            }
        }
    }

#pragma unroll
    for (int i = 0; i < 4; i++) {
        int qrow = qt * 64 + ty * 4 + i;
        float scale = qmask[b_ * Ss + qrow] / l_i[i];
        *(float4*)&out[(size_t)(b_ * Ss + qrow) * DM + h * 64 + tx * 4] =
            make_float4(acc[i][0] * scale, acc[i][1] * scale,
                        acc[i][2] * scale, acc[i][3] * scale);
    }
}

extern "C" void kernel_launch(void* const* d_in, const int* in_sizes, int n_in,
                              void* d_out, int out_size)
{
    const float* q     = (const float*)d_in[0];
    const float* k     = (const float*)d_in[1];
    const float* v     = (const float*)d_in[2];
    const float* vmask = (const float*)d_in[3];
    const float* qmask = (const float*)d_in[4];
    const float* Wq    = (const float*)d_in[5];
    const float* Wk    = (const float*)d_in[6];
    const float* Wv    = (const float*)d_in[7];
    float* out = (float*)d_out;

    dim3 cg(Bb * Ss * DM / (256 * 4), 3);
    cvt_kernel<<<cg, 256>>>(q, k, v);

    dim3 tg(DM / 32, DM / 32, 3);
    wt_kernel<<<tg, 256>>>(Wq, Wk, Wv);

    dim3 pg(DM / BN, (Bb * Ss) / BM, 3);
    proj_mma_kernel<<<pg, 256>>>();

    size_t smem = (size_t)(64 * 64 * 3 + 64 * KT_STRIDE + 64) * sizeof(float);
    cudaFuncSetAttribute(fa_kernel, cudaFuncAttributeMaxDynamicSharedMemorySize,
                         (int)smem);
    dim3 fg(Ss / 64, Bb * Hh);
    fa_kernel<<<fg, 256, smem>>>(vmask, qmask, out);
}

// round 4
// speedup vs baseline: 2.9733x; 1.9009x over previous
#include <cuda_runtime.h>
#include <cstdint>

#define Bb 4
#define Ss 2048
#define DM 1024
#define Hh 16
#define Dh 64
#define NEG_BIG 1e10f

// Scratch (allocation-free rule: __device__ globals).
__device__ float g_qw[Bb * Hh * Ss * Dh];
__device__ float g_kw[Bb * Hh * Ss * Dh];
__device__ float g_vw[Bb * Hh * Ss * Dh];
__device__ float g_Wt[3 * DM * DM];          // W^T [N,K], tf32-formatted
__device__ float g_Xt[3 * Bb * Ss * DM];     // inputs, tf32-formatted

__device__ __forceinline__ uint32_t smem_u32(const void* p) {
    uint32_t a;
    asm("{ .reg .u64 t; cvta.to.shared.u64 t, %1; cvt.u32.u64 %0, t; }"
        : "=r"(a) : "l"(p));
    return a;
}
__device__ __forceinline__ uint32_t f2tf32(float f) {
    uint32_t r;
    asm("cvt.rna.tf32.f32 %0, %1;" : "=r"(r) : "f"(f));
    return r;
}
__device__ __forceinline__ void cp_async16(uint32_t dst, const void* src) {
    asm volatile("cp.async.cg.shared.global [%0], [%1], 16;"
                 :: "r"(dst), "l"(src) : "memory");
}
__device__ __forceinline__ void mma_tf32(float* d, const uint32_t* a,
                                         const uint32_t* b) {
    asm volatile(
        "mma.sync.aligned.m16n8k8.row.col.f32.tf32.tf32.f32 "
        "{%0,%1,%2,%3}, {%4,%5,%6,%7}, {%8,%9}, {%0,%1,%2,%3};"
        : "+f"(d[0]), "+f"(d[1]), "+f"(d[2]), "+f"(d[3])
        : "r"(a[0]), "r"(a[1]), "r"(a[2]), "r"(a[3]), "r"(b[0]), "r"(b[1]));
}

// ---------------------------------------------------------------------------
// Pre-pass 1: convert inputs to tf32-formatted fp32 in g_Xt.
// ---------------------------------------------------------------------------
__global__ __launch_bounds__(256)
void cvt_kernel(const float* __restrict__ q, const float* __restrict__ k,
                const float* __restrict__ v)
{
    const float* src = (blockIdx.y == 0) ? q : (blockIdx.y == 1) ? k : v;
    float* dst = g_Xt + (size_t)blockIdx.y * (Bb * Ss * DM);
    size_t i = ((size_t)blockIdx.x * 256 + threadIdx.x) * 4;
    float4 x = *(const float4*)&src[i];
    uint4 t = make_uint4(f2tf32(x.x), f2tf32(x.y), f2tf32(x.z), f2tf32(x.w));
    *(uint4*)&dst[i] = t;
}

// ---------------------------------------------------------------------------
// Pre-pass 2: Wt[n*DM + k] = tf32(W[k*DM + n])
// ---------------------------------------------------------------------------
__global__ __launch_bounds__(256)
void wt_kernel(const float* __restrict__ Wq, const float* __restrict__ Wk,
               const float* __restrict__ Wv)
{
    const float* W = (blockIdx.z == 0) ? Wq : (blockIdx.z == 1) ? Wk : Wv;
    float* Wt = g_Wt + (size_t)blockIdx.z * DM * DM;
    __shared__ float t[32][33];
    int x0 = blockIdx.x * 32, y0 = blockIdx.y * 32;
    int tx = threadIdx.x & 31, ty = threadIdx.x >> 5;  // 32 x 8
#pragma unroll
    for (int i = 0; i < 4; i++)
        t[ty + i * 8][tx] = W[(y0 + ty + i * 8) * DM + x0 + tx];
    __syncthreads();
#pragma unroll
    for (int i = 0; i < 4; i++)
        Wt[(x0 + ty + i * 8) * DM + y0 + tx] =
            __uint_as_float(f2tf32(t[tx][ty + i * 8]));
}

// ---------------------------------------------------------------------------
// Projection GEMM: mma.sync tf32. CTA 128x128, BK=16, 8 warps (2x4),
// warp tile 64x32. cp.async double-buffered smem, KP=20 pad.
// Outputs rounded to tf32 (consumed only as MMA operands in fa).
// ---------------------------------------------------------------------------
#define BM 128
#define BN 128
#define BK 16
#define KP 20

__global__ __launch_bounds__(256, 2)
void proj_mma_kernel()
{
    __shared__ float As[2][BM * KP];
    __shared__ float Bs[2][BN * KP];

    const int z = blockIdx.z;
    const float* X  = g_Xt + (size_t)z * (Bb * Ss * DM);
    const float* Wt = g_Wt + (size_t)z * DM * DM;
    float* O = (z == 0) ? g_qw : (z == 1) ? g_kw : g_vw;

    const int m0 = blockIdx.y * BM;
    const int n0 = blockIdx.x * BN;
    const int tid = threadIdx.x;
    const int lane = tid & 31;
    const int warp = tid >> 5;
    const int wm = (warp >> 2) * 64;
    const int wn = (warp & 3) * 32;

    const int lr = tid >> 2;
    const int lk = (tid & 3) * 4;

    const uint32_t sA0 = smem_u32(&As[0][0]);
    const uint32_t sA1 = smem_u32(&As[1][0]);
    const uint32_t sB0 = smem_u32(&Bs[0][0]);
    const uint32_t sB1 = smem_u32(&Bs[1][0]);

    float acc[4][4][4];
#pragma unroll
    for (int i = 0; i < 4; i++)
#pragma unroll
        for (int j = 0; j < 4; j++)
#pragma unroll
            for (int c = 0; c < 4; c++) acc[i][j][c] = 0.f;

    auto issue = [&](int kt, int bsel) {
        const int k0 = kt * BK;
        const uint32_t dA = bsel ? sA1 : sA0;
        const uint32_t dB = bsel ? sB1 : sB0;
        cp_async16(dA + (uint32_t)(lr * KP + lk) * 4,
                   &X[(size_t)(m0 + lr) * DM + k0 + lk]);
        cp_async16(dA + (uint32_t)((lr + 64) * KP + lk) * 4,
                   &X[(size_t)(m0 + lr + 64) * DM + k0 + lk]);
        cp_async16(dB + (uint32_t)(lr * KP + lk) * 4,
                   &Wt[(size_t)(n0 + lr) * DM + k0 + lk]);
        cp_async16(dB + (uint32_t)((lr + 64) * KP + lk) * 4,
                   &Wt[(size_t)(n0 + lr + 64) * DM + k0 + lk]);
        asm volatile("cp.async.commit_group;" ::: "memory");
    };

    issue(0, 0);

    for (int kt = 0; kt < DM / BK; kt++) {
        const int b = kt & 1;
        asm volatile("cp.async.wait_group 0;" ::: "memory");
        __syncthreads();
        if (kt + 1 < DM / BK) issue(kt + 1, b ^ 1);

        const float* as = &As[b][0];
        const float* bs = &Bs[b][0];
#pragma unroll
        for (int ks = 0; ks < 2; ks++) {
            uint32_t a[4][4];
#pragma unroll
            for (int mf = 0; mf < 4; mf++) {
                const float* p =
                    &as[(wm + mf * 16 + (lane >> 2)) * KP + ks * 8 + (lane & 3)];
                a[mf][0] = __float_as_uint(p[0]);
                a[mf][1] = __float_as_uint(p[8 * KP]);
                a[mf][2] = __float_as_uint(p[4]);
                a[mf][3] = __float_as_uint(p[8 * KP + 4]);
            }
            uint32_t bb[4][2];
#pragma unroll
            for (int nf = 0; nf < 4; nf++) {
                const float* p =
                    &bs[(wn + nf * 8 + (lane >> 2)) * KP + ks * 8 + (lane & 3)];
                bb[nf][0] = __float_as_uint(p[0]);
                bb[nf][1] = __float_as_uint(p[4]);
            }
#pragma unroll
            for (int mf = 0; mf < 4; mf++)
#pragma unroll
                for (int nf = 0; nf < 4; nf++)
                    mma_tf32(acc[mf][nf], a[mf], bb[nf]);
        }
        __syncthreads();
    }

#pragma unroll
    for (int mf = 0; mf < 4; mf++) {
#pragma unroll
        for (int nf = 0; nf < 4; nf++) {
            int m = m0 + wm + mf * 16 + (lane >> 2);
            int n = n0 + wn + nf * 8 + 2 * (lane & 3);
            int b_ = m >> 11, s = m & 2047, h = n >> 6, d = n & 63;
            float* op = &O[((((size_t)b_ * Hh + h) * Ss) + s) * Dh + d];
            *(float2*)op = make_float2(
                __uint_as_float(f2tf32(acc[mf][nf][0])),
                __uint_as_float(f2tf32(acc[mf][nf][1])));
            *(float2*)(op + 8 * Dh) = make_float2(
                __uint_as_float(f2tf32(acc[mf][nf][2])),
                __uint_as_float(f2tf32(acc[mf][nf][3])));
        }
    }
}

// ---------------------------------------------------------------------------
// Flash attention on mma.sync tf32. CTA = 128 q-rows x (b,h), kv tiles of 64,
// 8 warps x 16 q-rows. Q frags register-resident; K/V double-buffered cp.async.
// Smem strides: K/Q 68 (banks 4g+t), V 72 (banks 8t+g) -> conflict-free.
// ---------------------------------------------------------------------------
#define SPK 68
#define SPV 72
// floats: Qs[128*68]=8704, K0,K1[64*68]=4352 ea, V0,V1[64*72]=4608 ea, vm[64]x2
#define FA_SMEM_FLOATS (8704 + 2 * 4352 + 2 * 4608 + 128)

__global__ __launch_bounds__(256, 1)
void fa_mma_kernel(const float* __restrict__ vmask,
                   const float* __restrict__ qmask, float* __restrict__ out)
{
    extern __shared__ float sm[];
    float* Qs = sm;
    float* Kb0 = sm + 8704;
    float* Kb1 = Kb0 + 4352;
    float* Vb0 = Kb1 + 4352;
    float* Vb1 = Vb0 + 4608;
    float* vm0b = Vb1 + 4608;
    float* vm1b = vm0b + 64;

    const int qt = (int)gridDim.x - 1 - (int)blockIdx.x;  // heavy tiles first
    const int bh = blockIdx.y;
    const int b_ = bh >> 4, h = bh & 15;
    const int tid = threadIdx.x, lane = tid & 31, wid = tid >> 5;
    const int g = lane >> 2, t = lane & 3;

    const uint32_t uK[2] = { smem_u32(Kb0), smem_u32(Kb1) };
    const uint32_t uV[2] = { smem_u32(Vb0), smem_u32(Vb1) };
    const uint32_t uM[2] = { smem_u32(vm0b), smem_u32(vm1b) };

    const float* Kg = &g_kw[(size_t)bh * Ss * Dh];
    const float* Vg = &g_vw[(size_t)bh * Ss * Dh];

    const int lrow = tid >> 2;        // 0..63
    const int lf = (tid & 3) * 16;    // float col base, 16 floats per thread

    auto issue = [&](int jt, int bsel) {
#pragma unroll
        for (int i = 0; i < 4; i++) {
            int c = lf + i * 4;
            cp_async16(uK[bsel] + (uint32_t)(lrow * SPK + c) * 4,
                       Kg + (size_t)(jt * 64 + lrow) * Dh + c);
            cp_async16(uV[bsel] + (uint32_t)(lrow * SPV + c) * 4,
                       Vg + (size_t)(jt * 64 + lrow) * Dh + c);
        }
        if (tid < 16)
            cp_async16(uM[bsel] + tid * 16,
                       vmask + (size_t)b_ * Ss + jt * 64 + tid * 4);
        asm volatile("cp.async.commit_group;" ::: "memory");
    };

    issue(0, 0);

    // Load Q tile to smem (coalesced), then extract register fragments.
    {
        const float* Qg = &g_qw[((size_t)bh * Ss + qt * 128) * Dh];
#pragma unroll
        for (int i = 0; i < 8; i++) {
            int idx = tid + i * 256;       // float4 index, 2048 total
            int row = idx >> 4;
            int c = (idx & 15) * 4;
            *(float4*)&Qs[row * SPK + c] = *(const float4*)&Qg[row * Dh + c];
        }
    }
    __syncthreads();

    uint32_t qf[8][4];
    const int wr = wid * 16;
#pragma unroll
    for (int ks = 0; ks < 8; ks++) {
        const float* p = &Qs[(wr + g) * SPK + ks * 8 + t];
        qf[ks][0] = __float_as_uint(p[0]);
        qf[ks][1] = __float_as_uint(p[8 * SPK]);
        qf[ks][2] = __float_as_uint(p[4]);
        qf[ks][3] = __float_as_uint(p[8 * SPK + 4]);
    }

    const float NEG_INF = -__int_as_float(0x7f800000);
    float m0 = NEG_INF, m1 = NEG_INF, l0 = 0.f, l1 = 0.f;
    float o[8][4];
#pragma unroll
    for (int i = 0; i < 8; i++)
#pragma unroll
        for (int j = 0; j < 4; j++) o[i][j] = 0.f;

    const int r0 = qt * 128 + wid * 16 + g;
    const int r1 = r0 + 8;
    const int src0 = (lane & ~3) | (t >> 1);
    const int src1 = src0 + 2;
    const bool odd = t & 1;

    const int nt = 2 * qt + 2;
    for (int jt = 0; jt < nt; jt++) {
        const int bsel = jt & 1;
        asm volatile("cp.async.wait_group 0;" ::: "memory");
        __syncthreads();
        if (jt + 1 < nt) issue(jt + 1, bsel ^ 1);

        const float* ksm = bsel ? Kb1 : Kb0;
        const float* vsm = bsel ? Vb1 : Vb0;
        const float* vmp = bsel ? vm1b : vm0b;

        // S = Q @ K^T
        float s[8][4];
#pragma unroll
        for (int n = 0; n < 8; n++)
#pragma unroll
            for (int j = 0; j < 4; j++) s[n][j] = 0.f;
#pragma unroll
        for (int ks = 0; ks < 8; ks++) {
#pragma unroll
            for (int n = 0; n < 8; n++) {
                uint32_t bb[2];
                const float* kp = &ksm[(n * 8 + g) * SPK + ks * 8 + t];
                bb[0] = __float_as_uint(kp[0]);
                bb[1] = __float_as_uint(kp[4]);
                mma_tf32(s[n], qf[ks], bb);
            }
        }

        // scale + masks
        const bool cneed = (jt * 64 + 63) > (qt * 128 + wid * 16);
        float rm0 = NEG_INF, rm1 = NEG_INF;
#pragma unroll
        for (int n = 0; n < 8; n++) {
            float vmv0 = vmp[n * 8 + 2 * t];
            float vmv1 = vmp[n * 8 + 2 * t + 1];
            int c0 = jt * 64 + n * 8 + 2 * t;
            float s0 = s[n][0] * 0.125f - (1.f - vmv0) * NEG_BIG;
            float s1 = s[n][1] * 0.125f - (1.f - vmv1) * NEG_BIG;
            float s2 = s[n][2] * 0.125f - (1.f - vmv0) * NEG_BIG;
            float s3 = s[n][3] * 0.125f - (1.f - vmv1) * NEG_BIG;
            if (cneed) {
                if (c0 > r0) s0 -= NEG_BIG;
                if (c0 + 1 > r0) s1 -= NEG_BIG;
                if (c0 > r1) s2 -= NEG_BIG;
                if (c0 + 1 > r1) s3 -= NEG_BIG;
            }
            s[n][0] = s0; s[n][1] = s1; s[n][2] = s2; s[n][3] = s3;
            rm0 = fmaxf(rm0, fmaxf(s0, s1));
            rm1 = fmaxf(rm1, fmaxf(s2, s3));
        }
        rm0 = fmaxf(rm0, __shfl_xor_sync(0xffffffffu, rm0, 1));
        rm0 = fmaxf(rm0, __shfl_xor_sync(0xffffffffu, rm0, 2));
        rm1 = fmaxf(rm1, __shfl_xor_sync(0xffffffffu, rm1, 1));
        rm1 = fmaxf(rm1, __shfl_xor_sync(0xffffffffu, rm1, 2));

        float mn0 = fmaxf(m0, rm0), mn1 = fmaxf(m1, rm1);
        float cr0 = __expf(m0 - mn0), cr1 = __expf(m1 - mn1);
        float rs0 = 0.f, rs1 = 0.f;
#pragma unroll
        for (int n = 0; n < 8; n++) {
            s[n][0] = __expf(s[n][0] - mn0);
            s[n][1] = __expf(s[n][1] - mn0);
            s[n][2] = __expf(s[n][2] - mn1);
            s[n][3] = __expf(s[n][3] - mn1);
            rs0 += s[n][0] + s[n][1];
            rs1 += s[n][2] + s[n][3];
        }
        rs0 += __shfl_xor_sync(0xffffffffu, rs0, 1);
        rs0 += __shfl_xor_sync(0xffffffffu, rs0, 2);
        rs1 += __shfl_xor_sync(0xffffffffu, rs1, 1);
        rs1 += __shfl_xor_sync(0xffffffffu, rs1, 2);
        l0 = l0 * cr0 + rs0;
        l1 = l1 * cr1 + rs1;
        m0 = mn0; m1 = mn1;
#pragma unroll
        for (int nd = 0; nd < 8; nd++) {
            o[nd][0] *= cr0; o[nd][1] *= cr0;
            o[nd][2] *= cr1; o[nd][3] *= cr1;
        }

        // O += P @ V  (P accum frag -> A frag via quad shuffles)
#pragma unroll
        for (int kb = 0; kb < 8; kb++) {
            float x0 = __shfl_sync(0xffffffffu, s[kb][0], src0);
            float x1 = __shfl_sync(0xffffffffu, s[kb][1], src0);
            float x2 = __shfl_sync(0xffffffffu, s[kb][2], src0);
            float x3 = __shfl_sync(0xffffffffu, s[kb][3], src0);
            float y0 = __shfl_sync(0xffffffffu, s[kb][0], src1);
            float y1 = __shfl_sync(0xffffffffu, s[kb][1], src1);
            float y2 = __shfl_sync(0xffffffffu, s[kb][2], src1);
            float y3 = __shfl_sync(0xffffffffu, s[kb][3], src1);
            uint32_t a[4];
            a[0] = f2tf32(odd ? x1 : x0);
            a[1] = f2tf32(odd ? x3 : x2);
            a[2] = f2tf32(odd ? y1 : y0);
            a[3] = f2tf32(odd ? y3 : y2);
#pragma unroll
            for (int nd = 0; nd < 8; nd++) {
                uint32_t bb[2];
                const float* vp = &vsm[(kb * 8 + t) * SPV + nd * 8 + g];
                bb[0] = __float_as_uint(vp[0]);
                bb[1] = __float_as_uint(vp[4 * SPV]);
                mma_tf32(o[nd], a, bb);
            }
        }
    }

    // Epilogue
    float qm0 = qmask[(size_t)b_ * Ss + r0];
    float qm1 = qmask[(size_t)b_ * Ss + r1];
    float sc0 = qm0 / l0, sc1 = qm1 / l1;
    float* ob0 = out + ((size_t)b_ * Ss + r0) * DM + h * 64;
    float* ob1 = out + ((size_t)b_ * Ss + r1) * DM + h * 64;
#pragma unroll
    for (int nd = 0; nd < 8; nd++) {
        *(float2*)&ob0[nd * 8 + 2 * t] =
            make_float2(o[nd][0] * sc0, o[nd][1] * sc0);
        *(float2*)&ob1[nd * 8 + 2 * t] =
            make_float2(o[nd][2] * sc1, o[nd][3] * sc1);
    }
}

extern "C" void kernel_launch(void* const* d_in, const int* in_sizes, int n_in,
                              void* d_out, int out_size)
{
    const float* q     = (const float*)d_in[0];
    const float* k     = (const float*)d_in[1];
    const float* v     = (const float*)d_in[2];
    const float* vmask = (const float*)d_in[3];
    const float* qmask = (const float*)d_in[4];
    const float* Wq    = (const float*)d_in[5];
    const float* Wk    = (const float*)d_in[6];
    const float* Wv    = (const float*)d_in[7];
    float* out = (float*)d_out;

    dim3 cg(Bb * Ss * DM / (256 * 4), 3);
    cvt_kernel<<<cg, 256>>>(q, k, v);

    dim3 tg(DM / 32, DM / 32, 3);
    wt_kernel<<<tg, 256>>>(Wq, Wk, Wv);

    dim3 pg(DM / BN, (Bb * Ss) / BM, 3);
    proj_mma_kernel<<<pg, 256>>>();

    int fa_smem = FA_SMEM_FLOATS * sizeof(float);
    cudaFuncSetAttribute(fa_mma_kernel,
                         cudaFuncAttributeMaxDynamicSharedMemorySize, fa_smem);
    dim3 fg(Ss / 128, Bb * Hh);
    fa_mma_kernel<<<fg, 256, fa_smem>>>(vmask, qmask, out);
}

// round 6
// speedup vs baseline: 3.2439x; 1.0910x over previous
#include <cuda_runtime.h>
#include <cuda_fp16.h>
#include <cstdint>

#define Bb 4
#define Ss 2048
#define DM 1024
#define Hh 16
#define Dh 64
#define NEG_BIG 1e10f
// base-2 domain constants
#define SCALE2 0.18033688011112042f   /* 0.125 * log2(e) */
#define BIG2   1.4426950408889634e10f /* NEG_BIG * log2(e) */

// Scratch (allocation-free rule: __device__ globals).
__device__ float  g_qw[Bb * Hh * Ss * Dh];   // k-interleaved within 8-blocks
__device__ float  g_kw[Bb * Hh * Ss * Dh];   // k-interleaved within 8-blocks
__device__ __half g_vh[Bb * Hh * Ss * Dh];   // fp16 V
__device__ float  g_Wt[3 * DM * DM];         // W^T [N,K], tf32-formatted
__device__ float  g_Xt[3 * Bb * Ss * DM];    // inputs, tf32-formatted

__device__ __forceinline__ uint32_t smem_u32(const void* p) {
    uint32_t a;
    asm("{ .reg .u64 t; cvta.to.shared.u64 t, %1; cvt.u32.u64 %0, t; }"
        : "=r"(a) : "l"(p));
    return a;
}
__device__ __forceinline__ uint32_t f2tf32(float f) {
    uint32_t r;
    asm("cvt.rna.tf32.f32 %0, %1;" : "=r"(r) : "f"(f));
    return r;
}
__device__ __forceinline__ float ex2f(float x) {
    float r;
    asm("ex2.approx.ftz.f32 %0, %1;" : "=f"(r) : "f"(x));
    return r;
}
__device__ __forceinline__ uint32_t packh2(float lo, float hi) {
    uint32_t r;  // d<15:0> = cvt(b-operand), d<31:16> = cvt(a-operand)
    asm("cvt.rn.f16x2.f32 %0, %1, %2;" : "=r"(r) : "f"(hi), "f"(lo));
    return r;
}
__device__ __forceinline__ void cp_async16(uint32_t dst, const void* src) {
    asm volatile("cp.async.cg.shared.global [%0], [%1], 16;"
                 :: "r"(dst), "l"(src) : "memory");
}
__device__ __forceinline__ void mma_tf32(float* d, const uint32_t* a,
                                         const uint32_t* b) {
    asm volatile(
        "mma.sync.aligned.m16n8k8.row.col.f32.tf32.tf32.f32 "
        "{%0,%1,%2,%3}, {%4,%5,%6,%7}, {%8,%9}, {%0,%1,%2,%3};"
        : "+f"(d[0]), "+f"(d[1]), "+f"(d[2]), "+f"(d[3])
        : "r"(a[0]), "r"(a[1]), "r"(a[2]), "r"(a[3]), "r"(b[0]), "r"(b[1]));
}
__device__ __forceinline__ void mma_f16(float* d, uint32_t a0, uint32_t a1,
                                        uint32_t a2, uint32_t a3,
                                        uint32_t b0, uint32_t b1) {
    asm volatile(
        "mma.sync.aligned.m16n8k16.row.col.f32.f16.f16.f32 "
        "{%0,%1,%2,%3}, {%4,%5,%6,%7}, {%8,%9}, {%0,%1,%2,%3};"
        : "+f"(d[0]), "+f"(d[1]), "+f"(d[2]), "+f"(d[3])
        : "r"(a0), "r"(a1), "r"(a2), "r"(a3), "r"(b0), "r"(b1));
}

// ---------------------------------------------------------------------------
// Pre-pass 1: convert inputs to tf32-formatted fp32 in g_Xt.
// ---------------------------------------------------------------------------
__global__ __launch_bounds__(256)
void cvt_kernel(const float* __restrict__ q, const float* __restrict__ k,
                const float* __restrict__ v)
{
    const float* src = (blockIdx.y == 0) ? q : (blockIdx.y == 1) ? k : v;
    float* dst = g_Xt + (size_t)blockIdx.y * (Bb * Ss * DM);
    size_t i = ((size_t)blockIdx.x * 256 + threadIdx.x) * 4;
    float4 x = *(const float4*)&src[i];
    uint4 t = make_uint4(f2tf32(x.x), f2tf32(x.y), f2tf32(x.z), f2tf32(x.w));
    *(uint4*)&dst[i] = t;
}

// ---------------------------------------------------------------------------
// Pre-pass 2: Wt[n*DM + k] = tf32(W[k*DM + n])
// ---------------------------------------------------------------------------
__global__ __launch_bounds__(256)
void wt_kernel(const float* __restrict__ Wq, const float* __restrict__ Wk,
               const float* __restrict__ Wv)
{
    const float* W = (blockIdx.z == 0) ? Wq : (blockIdx.z == 1) ? Wk : Wv;
    float* Wt = g_Wt + (size_t)blockIdx.z * DM * DM;
    __shared__ float t[32][33];
    int x0 = blockIdx.x * 32, y0 = blockIdx.y * 32;
    int tx = threadIdx.x & 31, ty = threadIdx.x >> 5;
#pragma unroll
    for (int i = 0; i < 4; i++)
        t[ty + i * 8][tx] = W[(y0 + ty + i * 8) * DM + x0 + tx];
    __syncthreads();
#pragma unroll
    for (int i = 0; i < 4; i++)
        Wt[(x0 + ty + i * 8) * DM + y0 + tx] =
            __uint_as_float(f2tf32(t[tx][ty + i * 8]));
}

// ---------------------------------------------------------------------------
// Projection GEMM (mma.sync tf32). Epilogue:
//   z=0,1 (Q,K): tf32-round + k-interleave d within 8-blocks (j<4->2j else 2j-7)
//   z=2   (V):   convert to fp16 into g_vh
// ---------------------------------------------------------------------------
#define BM 128
#define BN 128
#define BK 16
#define KP 20

__global__ __launch_bounds__(256, 2)
void proj_mma_kernel()
{
    __shared__ float As[2][BM * KP];
    __shared__ float Bs[2][BN * KP];

    const int z = blockIdx.z;
    const float* X  = g_Xt + (size_t)z * (Bb * Ss * DM);
    const float* Wt = g_Wt + (size_t)z * DM * DM;
    float* O = (z == 0) ? g_qw : g_kw;

    const int m0 = blockIdx.y * BM;
    const int n0 = blockIdx.x * BN;
    const int tid = threadIdx.x;
    const int lane = tid & 31;
    const int warp = tid >> 5;
    const int wm = (warp >> 2) * 64;
    const int wn = (warp & 3) * 32;

    const int lr = tid >> 2;
    const int lk = (tid & 3) * 4;

    const uint32_t sA0 = smem_u32(&As[0][0]);
    const uint32_t sA1 = smem_u32(&As[1][0]);
    const uint32_t sB0 = smem_u32(&Bs[0][0]);
    const uint32_t sB1 = smem_u32(&Bs[1][0]);

    float acc[4][4][4];
#pragma unroll
    for (int i = 0; i < 4; i++)
#pragma unroll
        for (int j = 0; j < 4; j++)
#pragma unroll
            for (int c = 0; c < 4; c++) acc[i][j][c] = 0.f;

    auto issue = [&](int kt, int bsel) {
        const int k0 = kt * BK;
        const uint32_t dA = bsel ? sA1 : sA0;
        const uint32_t dB = bsel ? sB1 : sB0;
        cp_async16(dA + (uint32_t)(lr * KP + lk) * 4,
                   &X[(size_t)(m0 + lr) * DM + k0 + lk]);
        cp_async16(dA + (uint32_t)((lr + 64) * KP + lk) * 4,
                   &X[(size_t)(m0 + lr + 64) * DM + k0 + lk]);
        cp_async16(dB + (uint32_t)(lr * KP + lk) * 4,
                   &Wt[(size_t)(n0 + lr) * DM + k0 + lk]);
        cp_async16(dB + (uint32_t)((lr + 64) * KP + lk) * 4,
                   &Wt[(size_t)(n0 + lr + 64) * DM + k0 + lk]);
        asm volatile("cp.async.commit_group;" ::: "memory");
    };

    issue(0, 0);

    for (int kt = 0; kt < DM / BK; kt++) {
        const int b = kt & 1;
        asm volatile("cp.async.wait_group 0;" ::: "memory");
        __syncthreads();
        if (kt + 1 < DM / BK) issue(kt + 1, b ^ 1);

        const float* as = &As[b][0];
        const float* bs = &Bs[b][0];
#pragma unroll
        for (int ks = 0; ks < 2; ks++) {
            uint32_t a[4][4];
#pragma unroll
            for (int mf = 0; mf < 4; mf++) {
                const float* p =
                    &as[(wm + mf * 16 + (lane >> 2)) * KP + ks * 8 + (lane & 3)];
                a[mf][0] = __float_as_uint(p[0]);
                a[mf][1] = __float_as_uint(p[8 * KP]);
                a[mf][2] = __float_as_uint(p[4]);
                a[mf][3] = __float_as_uint(p[8 * KP + 4]);
            }
            uint32_t bb[4][2];
#pragma unroll
            for (int nf = 0; nf < 4; nf++) {
                const float* p =
                    &bs[(wn + nf * 8 + (lane >> 2)) * KP + ks * 8 + (lane & 3)];
                bb[nf][0] = __float_as_uint(p[0]);
                bb[nf][1] = __float_as_uint(p[4]);
            }
#pragma unroll
            for (int mf = 0; mf < 4; mf++)
#pragma unroll
                for (int nf = 0; nf < 4; nf++)
                    mma_tf32(acc[mf][nf], a[mf], bb[nf]);
        }
        __syncthreads();
    }

    // j0 = 2*(lane&3) in {0,2,4,6}; perm: j<4 -> 2j, else 2j-7
    const int j0 = 2 * (lane & 3);
    const int p0 = (j0 < 4) ? 2 * j0 : 2 * j0 - 7;

#pragma unroll
    for (int mf = 0; mf < 4; mf++) {
#pragma unroll
        for (int nf = 0; nf < 4; nf++) {
            int m = m0 + wm + mf * 16 + (lane >> 2);
            int n = n0 + wn + nf * 8 + j0;
            int b_ = m >> 11, s = m & 2047, h = n >> 6, d = n & 63;
            size_t base = ((((size_t)b_ * Hh + h) * Ss) + s) * Dh;
            if (z < 2) {
                int dp = (d & ~7) + p0;
                float* op = &O[base + dp];
                op[0] = __uint_as_float(f2tf32(acc[mf][nf][0]));
                op[2] = __uint_as_float(f2tf32(acc[mf][nf][1]));
                float* op8 = op + 8 * Dh;
                op8[0] = __uint_as_float(f2tf32(acc[mf][nf][2]));
                op8[2] = __uint_as_float(f2tf32(acc[mf][nf][3]));
            } else {
                __half* vp = &g_vh[base + d];
                *(__half2*)vp =
                    __floats2half2_rn(acc[mf][nf][0], acc[mf][nf][1]);
                *(__half2*)(vp + 8 * Dh) =
                    __floats2half2_rn(acc[mf][nf][2], acc[mf][nf][3]);
            }
        }
    }
}

// ---------------------------------------------------------------------------
// Flash attention: QK^T on tf32 mma (k-interleaved LDS.64 fragments),
// PV on fp16 m16n8k16 (S-accum -> A-frag pack, ldmatrix.trans for V).
// CTA = 128 q-rows x (b,h); 8 warps x 16 rows; kv tiles 64; 2 CTAs/SM.
// ---------------------------------------------------------------------------
#define SPK 68      /* K/Q smem stride in floats  */
#define SPVH 72     /* V smem stride in halves    */
// floats: Qs 8704 | Kb 2*4352=8704 | Vh 2 bufs * (64*72 halves = 2304 fl) = 4608 | vm 128
#define FA_SMEM_FLOATS (8704 + 8704 + 4608 + 128)

__global__ __launch_bounds__(256, 2)
void fa_mma_kernel(const float* __restrict__ vmask,
                   const float* __restrict__ qmask, float* __restrict__ out)
{
    extern __shared__ float sm[];
    float*  Qs   = sm;                    // 8704
    float*  Kb0  = sm + 8704;             // 4352
    float*  Kb1  = sm + 13056;            // 4352
    __half* Vh0  = (__half*)(sm + 17408); // 64*72 halves = 2304 floats
    __half* Vh1  = (__half*)(sm + 19712); // 64*72 halves = 2304 floats
    float*  vm0b = sm + 22016;
    float*  vm1b = sm + 22080;

    const int qt = (int)gridDim.x - 1 - (int)blockIdx.x;  // heavy tiles first
    const int bh = blockIdx.y;
    const int b_ = bh >> 4, h = bh & 15;
    const int tid = threadIdx.x, lane = tid & 31, wid = tid >> 5;
    const int g = lane >> 2, t = lane & 3;

    const uint32_t uQ = smem_u32(Qs);
    const uint32_t uK[2] = { smem_u32(Kb0), smem_u32(Kb1) };
    const uint32_t uV[2] = { smem_u32(Vh0), smem_u32(Vh1) };
    const uint32_t uM[2] = { smem_u32(vm0b), smem_u32(vm1b) };

    const float*  Kg = &g_kw[(size_t)bh * Ss * Dh];
    const __half* Vg = &g_vh[(size_t)bh * Ss * Dh];

    auto issue = [&](int jt, int bsel) {
        const int lrow = tid >> 2;
        const int lf = (tid & 3) * 16;
#pragma unroll
        for (int i = 0; i < 4; i++) {
            int c = lf + i * 4;
            cp_async16(uK[bsel] + (uint32_t)(lrow * SPK + c) * 4,
                       Kg + (size_t)(jt * 64 + lrow) * Dh + c);
        }
#pragma unroll
        for (int i = 0; i < 2; i++) {
            int idx = tid + i * 256;          // 512 16B-chunks for V
            int row = idx >> 3, c16 = idx & 7;
            cp_async16(uV[bsel] + (uint32_t)(row * SPVH * 2 + c16 * 16),
                       Vg + (size_t)(jt * 64 + row) * Dh + c16 * 8);
        }
        if (tid < 16)
            cp_async16(uM[bsel] + tid * 16,
                       vmask + (size_t)b_ * Ss + jt * 64 + tid * 4);
        asm volatile("cp.async.commit_group;" ::: "memory");
    };

    issue(0, 0);

    // Q tile -> smem via cp.async (2048 16B-chunks)
    {
        const float* Qg = &g_qw[((size_t)bh * Ss + qt * 128) * Dh];
#pragma unroll
        for (int i = 0; i < 8; i++) {
            int idx = tid + i * 256;
            int row = idx >> 4, c16 = idx & 15;
            cp_async16(uQ + (uint32_t)(row * SPK + c16 * 4) * 4,
                       Qg + (size_t)row * Dh + c16 * 4);
        }
        asm volatile("cp.async.commit_group;" ::: "memory");
    }

    const float NEG_INF = -__int_as_float(0x7f800000);
    float m0 = NEG_INF, m1 = NEG_INF, l0 = 0.f, l1 = 0.f;
    float o[8][4];
#pragma unroll
    for (int i = 0; i < 8; i++)
#pragma unroll
        for (int j = 0; j < 4; j++) o[i][j] = 0.f;

    const int r0 = qt * 128 + wid * 16 + g;
    const int r1 = r0 + 8;
    const int wr = wid * 16;
    // ldmatrix x4 per-lane base: tile = lane>>3 -> (row +8 if tile odd, col +8 if tile>=2)
    const uint32_t vtile_off =
        (uint32_t)(((lane & 7) + ((lane >> 3) & 1) * 8) * SPVH * 2 +
                   (lane >> 4) * 16);

    const int nt = 2 * qt + 2;
    for (int jt = 0; jt < nt; jt++) {
        const int bsel = jt & 1;
        asm volatile("cp.async.wait_group 0;" ::: "memory");
        __syncthreads();
        if (jt + 1 < nt) issue(jt + 1, bsel ^ 1);

        const float* ksm = bsel ? Kb1 : Kb0;
        const float* vmp = bsel ? vm1b : vm0b;
        const uint32_t vb = uV[bsel] + vtile_off;

        // S = Q @ K^T (tf32), frags via LDS.64 on k-interleaved layout
        float s[8][4];
#pragma unroll
        for (int n = 0; n < 8; n++)
#pragma unroll
            for (int j = 0; j < 4; j++) s[n][j] = 0.f;
#pragma unroll
        for (int ks = 0; ks < 8; ks++) {
            float2 a0p = *(const float2*)&Qs[(wr + g) * SPK + ks * 8 + 2 * t];
            float2 a1p = *(const float2*)&Qs[(wr + g + 8) * SPK + ks * 8 + 2 * t];
            uint32_t a[4] = { __float_as_uint(a0p.x), __float_as_uint(a1p.x),
                              __float_as_uint(a0p.y), __float_as_uint(a1p.y) };
#pragma unroll
            for (int n = 0; n < 8; n++) {
                float2 bp = *(const float2*)&ksm[(n * 8 + g) * SPK + ks * 8 + 2 * t];
                uint32_t bb[2] = { __float_as_uint(bp.x), __float_as_uint(bp.y) };
                mma_tf32(s[n], a, bb);
            }
        }

        // scale + masks in base-2 domain
        const bool cneed = (jt * 64 + 63) > (qt * 128 + wid * 16);
        float rm0 = NEG_INF, rm1 = NEG_INF;
#pragma unroll
        for (int n = 0; n < 8; n++) {
            float vmv0 = vmp[n * 8 + 2 * t];
            float vmv1 = vmp[n * 8 + 2 * t + 1];
            int c0 = jt * 64 + n * 8 + 2 * t;
            float s0 = s[n][0] * SCALE2 - (1.f - vmv0) * BIG2;
            float s1 = s[n][1] * SCALE2 - (1.f - vmv1) * BIG2;
            float s2 = s[n][2] * SCALE2 - (1.f - vmv0) * BIG2;
            float s3 = s[n][3] * SCALE2 - (1.f - vmv1) * BIG2;
            if (cneed) {
                if (c0 > r0) s0 -= BIG2;
                if (c0 + 1 > r0) s1 -= BIG2;
                if (c0 > r1) s2 -= BIG2;
                if (c0 + 1 > r1) s3 -= BIG2;
            }
            s[n][0] = s0; s[n][1] = s1; s[n][2] = s2; s[n][3] = s3;
            rm0 = fmaxf(rm0, fmaxf(s0, s1));
            rm1 = fmaxf(rm1, fmaxf(s2, s3));
        }
        rm0 = fmaxf(rm0, __shfl_xor_sync(0xffffffffu, rm0, 1));
        rm0 = fmaxf(rm0, __shfl_xor_sync(0xffffffffu, rm0, 2));
        rm1 = fmaxf(rm1, __shfl_xor_sync(0xffffffffu, rm1, 1));
        rm1 = fmaxf(rm1, __shfl_xor_sync(0xffffffffu, rm1, 2));

        float mn0 = fmaxf(m0, rm0), mn1 = fmaxf(m1, rm1);
        float cr0 = ex2f(m0 - mn0), cr1 = ex2f(m1 - mn1);
        float rs0 = 0.f, rs1 = 0.f;
#pragma unroll
        for (int n = 0; n < 8; n++) {
            s[n][0] = ex2f(s[n][0] - mn0);
            s[n][1] = ex2f(s[n][1] - mn0);
            s[n][2] = ex2f(s[n][2] - mn1);
            s[n][3] = ex2f(s[n][3] - mn1);
            rs0 += s[n][0] + s[n][1];
            rs1 += s[n][2] + s[n][3];
        }
        rs0 += __shfl_xor_sync(0xffffffffu, rs0, 1);
        rs0 += __shfl_xor_sync(0xffffffffu, rs0, 2);
        rs1 += __shfl_xor_sync(0xffffffffu, rs1, 1);
        rs1 += __shfl_xor_sync(0xffffffffu, rs1, 2);
        l0 = l0 * cr0 + rs0;
        l1 = l1 * cr1 + rs1;
        m0 = mn0; m1 = mn1;
#pragma unroll
        for (int nd = 0; nd < 8; nd++) {
            o[nd][0] *= cr0; o[nd][1] *= cr0;
            o[nd][2] *= cr1; o[nd][3] *= cr1;
        }

        // O += P @ V : fp16 m16n8k16; A = packed S frags, B via ldmatrix.trans
#pragma unroll
        for (int kb = 0; kb < 4; kb++) {
            uint32_t a0 = packh2(s[2 * kb][0], s[2 * kb][1]);
            uint32_t a1 = packh2(s[2 * kb][2], s[2 * kb][3]);
            uint32_t a2 = packh2(s[2 * kb + 1][0], s[2 * kb + 1][1]);
            uint32_t a3 = packh2(s[2 * kb + 1][2], s[2 * kb + 1][3]);
            uint32_t rowoff = (uint32_t)(kb * 16 * SPVH * 2);
#pragma unroll
            for (int dp = 0; dp < 4; dp++) {
                uint32_t b0, b1, b2, b3;
                asm volatile(
                    "ldmatrix.sync.aligned.m8n8.x4.trans.shared.b16 "
                    "{%0,%1,%2,%3}, [%4];"
                    : "=r"(b0), "=r"(b1), "=r"(b2), "=r"(b3)
                    : "r"(vb + rowoff + dp * 32));
                mma_f16(o[2 * dp], a0, a1, a2, a3, b0, b1);
                mma_f16(o[2 * dp + 1], a0, a1, a2, a3, b2, b3);
            }
        }
    }

    // Epilogue
    float qm0 = qmask[(size_t)b_ * Ss + r0];
    float qm1 = qmask[(size_t)b_ * Ss + r1];
    float sc0 = qm0 / l0, sc1 = qm1 / l1;
    float* ob0 = out + ((size_t)b_ * Ss + r0) * DM + h * 64;
    float* ob1 = out + ((size_t)b_ * Ss + r1) * DM + h * 64;
#pragma unroll
    for (int nd = 0; nd < 8; nd++) {
        *(float2*)&ob0[nd * 8 + 2 * t] =
            make_float2(o[nd][0] * sc0, o[nd][1] * sc0);
        *(float2*)&ob1[nd * 8 + 2 * t] =
            make_float2(o[nd][2] * sc1, o[nd][3] * sc1);
    }
}

extern "C" void kernel_launch(void* const* d_in, const int* in_sizes, int n_in,
                              void* d_out, int out_size)
{
    const float* q     = (const float*)d_in[0];
    const float* k     = (const float*)d_in[1];
    const float* v     = (const float*)d_in[2];
    const float* vmask = (const float*)d_in[3];
    const float* qmask = (const float*)d_in[4];
    const float* Wq    = (const float*)d_in[5];
    const float* Wk    = (const float*)d_in[6];
    const float* Wv    = (const float*)d_in[7];
    float* out = (float*)d_out;

    dim3 cg(Bb * Ss * DM / (256 * 4), 3);
    cvt_kernel<<<cg, 256>>>(q, k, v);

    dim3 tg(DM / 32, DM / 32, 3);
    wt_kernel<<<tg, 256>>>(Wq, Wk, Wv);

    dim3 pg(DM / BN, (Bb * Ss) / BM, 3);
    proj_mma_kernel<<<pg, 256>>>();

    int fa_smem = FA_SMEM_FLOATS * sizeof(float);
    cudaFuncSetAttribute(fa_mma_kernel,
                         cudaFuncAttributeMaxDynamicSharedMemorySize, fa_smem);
    dim3 fg(Ss / 128, Bb * Hh);
    fa_mma_kernel<<<fg, 256, fa_smem>>>(vmask, qmask, out);
}

// round 7
// speedup vs baseline: 3.5323x; 1.0889x over previous
#include <cuda_runtime.h>
#include <cuda_fp16.h>
#include <cstdint>

#define Bb 4
#define Ss 2048
#define DM 1024
#define Hh 16
#define Dh 64
#define NEG_BIG 1e10f
// base-2 domain constants
#define SCALE2 0.18033688011112042f   /* 0.125 * log2(e) */
#define BIG2   1.4426950408889634e10f /* NEG_BIG * log2(e) */

// Scratch (allocation-free rule: __device__ globals).
__device__ float  g_qw[Bb * Hh * Ss * Dh];   // k-interleaved within 8-blocks
__device__ float  g_kw[Bb * Hh * Ss * Dh];   // k-interleaved within 8-blocks
__device__ __half g_vh[Bb * Hh * Ss * Dh];   // fp16 V

__device__ __forceinline__ uint32_t smem_u32(const void* p) {
    uint32_t a;
    asm("{ .reg .u64 t; cvta.to.shared.u64 t, %1; cvt.u32.u64 %0, t; }"
        : "=r"(a) : "l"(p));
    return a;
}
__device__ __forceinline__ uint32_t f2tf32(float f) {
    uint32_t r;
    asm("cvt.rna.tf32.f32 %0, %1;" : "=r"(r) : "f"(f));
    return r;
}
__device__ __forceinline__ float ex2f(float x) {
    float r;
    asm("ex2.approx.ftz.f32 %0, %1;" : "=f"(r) : "f"(x));
    return r;
}
__device__ __forceinline__ uint32_t packh2(float lo, float hi) {
    uint32_t r;
    asm("cvt.rn.f16x2.f32 %0, %1, %2;" : "=r"(r) : "f"(hi), "f"(lo));
    return r;
}
__device__ __forceinline__ void cp_async16(uint32_t dst, const void* src) {
    asm volatile("cp.async.cg.shared.global [%0], [%1], 16;"
                 :: "r"(dst), "l"(src) : "memory");
}
__device__ __forceinline__ void mma_tf32(float* d, const uint32_t* a,
                                         const uint32_t* b) {
    asm volatile(
        "mma.sync.aligned.m16n8k8.row.col.f32.tf32.tf32.f32 "
        "{%0,%1,%2,%3}, {%4,%5,%6,%7}, {%8,%9}, {%0,%1,%2,%3};"
        : "+f"(d[0]), "+f"(d[1]), "+f"(d[2]), "+f"(d[3])
        : "r"(a[0]), "r"(a[1]), "r"(a[2]), "r"(a[3]), "r"(b[0]), "r"(b[1]));
}
__device__ __forceinline__ void mma_f16(float* d, uint32_t a0, uint32_t a1,
                                        uint32_t a2, uint32_t a3,
                                        uint32_t b0, uint32_t b1) {
    asm volatile(
        "mma.sync.aligned.m16n8k16.row.col.f32.f16.f16.f32 "
        "{%0,%1,%2,%3}, {%4,%5,%6,%7}, {%8,%9}, {%0,%1,%2,%3};"
        : "+f"(d[0]), "+f"(d[1]), "+f"(d[2]), "+f"(d[3])
        : "r"(a0), "r"(a1), "r"(a2), "r"(a3), "r"(b0), "r"(b1));
}

// ---------------------------------------------------------------------------
// Projection GEMM: raw fp32 X [M,K] and W [K,N] from d_in, cvt->tf32 per
// fragment in-register. CTA 128x128, BK=32, 3-stage cp.async ring.
// A smem pad 36 (banks 4g+t), B smem [K,N] pad 136 (banks 8t+g).
// Epilogue: z<2 -> tf32-round + k-interleave; z=2 -> fp16 V.
// ---------------------------------------------------------------------------
#define BK2 32
#define PA 36
#define PB 136
#define A_ST (128 * PA)          /* 4608 floats */
#define B_ST (BK2 * PB)          /* 4352 floats */
#define PROJ_SMEM_FLOATS (3 * (A_ST + B_ST))

__global__ __launch_bounds__(256, 2)
void proj_mma_kernel(const float* __restrict__ qin,
                     const float* __restrict__ kin,
                     const float* __restrict__ vin,
                     const float* __restrict__ Wq,
                     const float* __restrict__ Wk,
                     const float* __restrict__ Wv)
{
    extern __shared__ float psm[];
    const int z = blockIdx.z;
    const float* X = (z == 0) ? qin : (z == 1) ? kin : vin;
    const float* W = (z == 0) ? Wq : (z == 1) ? Wk : Wv;
    float* O = (z == 0) ? g_qw : g_kw;

    const int m0 = blockIdx.y * 128;
    const int n0 = blockIdx.x * 128;
    const int tid = threadIdx.x;
    const int lane = tid & 31;
    const int warp = tid >> 5;
    const int wm = (warp >> 2) * 64;
    const int wn = (warp & 3) * 32;
    const int g = lane >> 2, t = lane & 3;

    uint32_t uA[3], uB[3];
#pragma unroll
    for (int i = 0; i < 3; i++) {
        uA[i] = smem_u32(psm + i * (A_ST + B_ST));
        uB[i] = smem_u32(psm + i * (A_ST + B_ST) + A_ST);
    }

    float acc[4][4][4];
#pragma unroll
    for (int i = 0; i < 4; i++)
#pragma unroll
        for (int j = 0; j < 4; j++)
#pragma unroll
            for (int c = 0; c < 4; c++) acc[i][j][c] = 0.f;

    auto issue = [&](int kt) {
        const int st = kt % 3;
        const int k0 = kt * BK2;
        // A: 1024 chunks of 16B; row=idx>>3 (0..127), col4=(idx&7)*4
#pragma unroll
        for (int i = 0; i < 4; i++) {
            int idx = tid + i * 256;
            int row = idx >> 3, c4 = (idx & 7) * 4;
            cp_async16(uA[st] + (uint32_t)(row * PA + c4) * 4,
                       &X[(size_t)(m0 + row) * DM + k0 + c4]);
        }
        // B: 1024 chunks; row=idx>>5 (0..31), col4=(idx&31)*4
#pragma unroll
        for (int i = 0; i < 4; i++) {
            int idx = tid + i * 256;
            int row = idx >> 5, c4 = (idx & 31) * 4;
            cp_async16(uB[st] + (uint32_t)(row * PB + c4) * 4,
                       &W[(size_t)(k0 + row) * DM + n0 + c4]);
        }
        asm volatile("cp.async.commit_group;" ::: "memory");
    };

    issue(0);
    issue(1);

    const int NSTAGE = DM / BK2;   // 32
    for (int kt = 0; kt < NSTAGE; kt++) {
        asm volatile("cp.async.wait_group 1;" ::: "memory");
        __syncthreads();
        if (kt + 2 < NSTAGE) issue(kt + 2);

        const int st = kt % 3;
        const float* as = psm + st * (A_ST + B_ST);
        const float* bs = as + A_ST;
#pragma unroll
        for (int ks = 0; ks < 4; ks++) {
            uint32_t a[4][4];
#pragma unroll
            for (int mf = 0; mf < 4; mf++) {
                const float* p = &as[(wm + mf * 16 + g) * PA + ks * 8 + t];
                a[mf][0] = f2tf32(p[0]);
                a[mf][1] = f2tf32(p[8 * PA]);
                a[mf][2] = f2tf32(p[4]);
                a[mf][3] = f2tf32(p[8 * PA + 4]);
            }
            uint32_t bb[4][2];
#pragma unroll
            for (int nf = 0; nf < 4; nf++) {
                const float* p = &bs[(ks * 8 + t) * PB + wn + nf * 8 + g];
                bb[nf][0] = f2tf32(p[0]);
                bb[nf][1] = f2tf32(p[4 * PB]);
            }
#pragma unroll
            for (int mf = 0; mf < 4; mf++)
#pragma unroll
                for (int nf = 0; nf < 4; nf++)
                    mma_tf32(acc[mf][nf], a[mf], bb[nf]);
        }
        __syncthreads();
    }

    // j0 = 2*(lane&3); k-interleave perm: j<4 -> 2j, else 2j-7
    const int j0 = 2 * t;
    const int p0 = (j0 < 4) ? 2 * j0 : 2 * j0 - 7;

#pragma unroll
    for (int mf = 0; mf < 4; mf++) {
#pragma unroll
        for (int nf = 0; nf < 4; nf++) {
            int m = m0 + wm + mf * 16 + g;
            int n = n0 + wn + nf * 8 + j0;
            int b_ = m >> 11, s = m & 2047, h = n >> 6, d = n & 63;
            size_t base = ((((size_t)b_ * Hh + h) * Ss) + s) * Dh;
            if (z < 2) {
                int dp = (d & ~7) + p0;
                float* op = &O[base + dp];
                op[0] = __uint_as_float(f2tf32(acc[mf][nf][0]));
                op[2] = __uint_as_float(f2tf32(acc[mf][nf][1]));
                float* op8 = op + 8 * Dh;
                op8[0] = __uint_as_float(f2tf32(acc[mf][nf][2]));
                op8[2] = __uint_as_float(f2tf32(acc[mf][nf][3]));
            } else {
                __half* vp = &g_vh[base + d];
                *(__half2*)vp =
                    __floats2half2_rn(acc[mf][nf][0], acc[mf][nf][1]);
                *(__half2*)(vp + 8 * Dh) =
                    __floats2half2_rn(acc[mf][nf][2], acc[mf][nf][3]);
            }
        }
    }
}

// ---------------------------------------------------------------------------
// Flash attention (unchanged from R6): QK^T tf32 mma, PV fp16 m16n8k16.
// ---------------------------------------------------------------------------
#define SPK 68      /* K/Q smem stride in floats  */
#define SPVH 72     /* V smem stride in halves    */
#define FA_SMEM_FLOATS (8704 + 8704 + 4608 + 128)

__global__ __launch_bounds__(256, 2)
void fa_mma_kernel(const float* __restrict__ vmask,
                   const float* __restrict__ qmask, float* __restrict__ out)
{
    extern __shared__ float sm[];
    float*  Qs   = sm;                    // 8704
    float*  Kb0  = sm + 8704;             // 4352
    float*  Kb1  = sm + 13056;            // 4352
    __half* Vh0  = (__half*)(sm + 17408); // 64*72 halves = 2304 floats
    __half* Vh1  = (__half*)(sm + 19712);
    float*  vm0b = sm + 22016;
    float*  vm1b = sm + 22080;

    const int qt = (int)gridDim.x - 1 - (int)blockIdx.x;  // heavy tiles first
    const int bh = blockIdx.y;
    const int b_ = bh >> 4, h = bh & 15;
    const int tid = threadIdx.x, lane = tid & 31, wid = tid >> 5;
    const int g = lane >> 2, t = lane & 3;

    const uint32_t uQ = smem_u32(Qs);
    const uint32_t uK[2] = { smem_u32(Kb0), smem_u32(Kb1) };
    const uint32_t uV[2] = { smem_u32(Vh0), smem_u32(Vh1) };
    const uint32_t uM[2] = { smem_u32(vm0b), smem_u32(vm1b) };

    const float*  Kg = &g_kw[(size_t)bh * Ss * Dh];
    const __half* Vg = &g_vh[(size_t)bh * Ss * Dh];

    auto issue = [&](int jt, int bsel) {
        const int lrow = tid >> 2;
        const int lf = (tid & 3) * 16;
#pragma unroll
        for (int i = 0; i < 4; i++) {
            int c = lf + i * 4;
            cp_async16(uK[bsel] + (uint32_t)(lrow * SPK + c) * 4,
                       Kg + (size_t)(jt * 64 + lrow) * Dh + c);
        }
#pragma unroll
        for (int i = 0; i < 2; i++) {
            int idx = tid + i * 256;
            int row = idx >> 3, c16 = idx & 7;
            cp_async16(uV[bsel] + (uint32_t)(row * SPVH * 2 + c16 * 16),
                       Vg + (size_t)(jt * 64 + row) * Dh + c16 * 8);
        }
        if (tid < 16)
            cp_async16(uM[bsel] + tid * 16,
                       vmask + (size_t)b_ * Ss + jt * 64 + tid * 4);
        asm volatile("cp.async.commit_group;" ::: "memory");
    };

    issue(0, 0);

    {
        const float* Qg = &g_qw[((size_t)bh * Ss + qt * 128) * Dh];
#pragma unroll
        for (int i = 0; i < 8; i++) {
            int idx = tid + i * 256;
            int row = idx >> 4, c16 = idx & 15;
            cp_async16(uQ + (uint32_t)(row * SPK + c16 * 4) * 4,
                       Qg + (size_t)row * Dh + c16 * 4);
        }
        asm volatile("cp.async.commit_group;" ::: "memory");
    }

    const float NEG_INF = -__int_as_float(0x7f800000);
    float m0 = NEG_INF, m1 = NEG_INF, l0 = 0.f, l1 = 0.f;
    float o[8][4];
#pragma unroll
    for (int i = 0; i < 8; i++)
#pragma unroll
        for (int j = 0; j < 4; j++) o[i][j] = 0.f;

    const int r0 = qt * 128 + wid * 16 + g;
    const int r1 = r0 + 8;
    const int wr = wid * 16;
    const uint32_t vtile_off =
        (uint32_t)(((lane & 7) + ((lane >> 3) & 1) * 8) * SPVH * 2 +
                   (lane >> 4) * 16);

    const int nt = 2 * qt + 2;
    for (int jt = 0; jt < nt; jt++) {
        const int bsel = jt & 1;
        asm volatile("cp.async.wait_group 0;" ::: "memory");
        __syncthreads();
        if (jt + 1 < nt) issue(jt + 1, bsel ^ 1);

        const float* ksm = bsel ? Kb1 : Kb0;
        const float* vmp = bsel ? vm1b : vm0b;
        const uint32_t vb = uV[bsel] + vtile_off;

        float s[8][4];
#pragma unroll
        for (int n = 0; n < 8; n++)
#pragma unroll
            for (int j = 0; j < 4; j++) s[n][j] = 0.f;
#pragma unroll
        for (int ks = 0; ks < 8; ks++) {
            float2 a0p = *(const float2*)&Qs[(wr + g) * SPK + ks * 8 + 2 * t];
            float2 a1p = *(const float2*)&Qs[(wr + g + 8) * SPK + ks * 8 + 2 * t];
            uint32_t a[4] = { __float_as_uint(a0p.x), __float_as_uint(a1p.x),
                              __float_as_uint(a0p.y), __float_as_uint(a1p.y) };
#pragma unroll
            for (int n = 0; n < 8; n++) {
                float2 bp = *(const float2*)&ksm[(n * 8 + g) * SPK + ks * 8 + 2 * t];
                uint32_t bb[2] = { __float_as_uint(bp.x), __float_as_uint(bp.y) };
                mma_tf32(s[n], a, bb);
            }
        }

        const bool cneed = (jt * 64 + 63) > (qt * 128 + wid * 16);
        float rm0 = NEG_INF, rm1 = NEG_INF;
#pragma unroll
        for (int n = 0; n < 8; n++) {
            float vmv0 = vmp[n * 8 + 2 * t];
            float vmv1 = vmp[n * 8 + 2 * t + 1];
            int c0 = jt * 64 + n * 8 + 2 * t;
            float s0 = s[n][0] * SCALE2 - (1.f - vmv0) * BIG2;
            float s1 = s[n][1] * SCALE2 - (1.f - vmv1) * BIG2;
            float s2 = s[n][2] * SCALE2 - (1.f - vmv0) * BIG2;
            float s3 = s[n][3] * SCALE2 - (1.f - vmv1) * BIG2;
            if (cneed) {
                if (c0 > r0) s0 -= BIG2;
                if (c0 + 1 > r0) s1 -= BIG2;
                if (c0 > r1) s2 -= BIG2;
                if (c0 + 1 > r1) s3 -= BIG2;
            }
            s[n][0] = s0; s[n][1] = s1; s[n][2] = s2; s[n][3] = s3;
            rm0 = fmaxf(rm0, fmaxf(s0, s1));
            rm1 = fmaxf(rm1, fmaxf(s2, s3));
        }
        rm0 = fmaxf(rm0, __shfl_xor_sync(0xffffffffu, rm0, 1));
        rm0 = fmaxf(rm0, __shfl_xor_sync(0xffffffffu, rm0, 2));
        rm1 = fmaxf(rm1, __shfl_xor_sync(0xffffffffu, rm1, 1));
        rm1 = fmaxf(rm1, __shfl_xor_sync(0xffffffffu, rm1, 2));

        float mn0 = fmaxf(m0, rm0), mn1 = fmaxf(m1, rm1);
        float cr0 = ex2f(m0 - mn0), cr1 = ex2f(m1 - mn1);
        float rs0 = 0.f, rs1 = 0.f;
#pragma unroll
        for (int n = 0; n < 8; n++) {
            s[n][0] = ex2f(s[n][0] - mn0);
            s[n][1] = ex2f(s[n][1] - mn0);
            s[n][2] = ex2f(s[n][2] - mn1);
            s[n][3] = ex2f(s[n][3] - mn1);
            rs0 += s[n][0] + s[n][1];
            rs1 += s[n][2] + s[n][3];
        }
        rs0 += __shfl_xor_sync(0xffffffffu, rs0, 1);
        rs0 += __shfl_xor_sync(0xffffffffu, rs0, 2);
        rs1 += __shfl_xor_sync(0xffffffffu, rs1, 1);
        rs1 += __shfl_xor_sync(0xffffffffu, rs1, 2);
        l0 = l0 * cr0 + rs0;
        l1 = l1 * cr1 + rs1;
        m0 = mn0; m1 = mn1;
#pragma unroll
        for (int nd = 0; nd < 8; nd++) {
            o[nd][0] *= cr0; o[nd][1] *= cr0;
            o[nd][2] *= cr1; o[nd][3] *= cr1;
        }

#pragma unroll
        for (int kb = 0; kb < 4; kb++) {
            uint32_t a0 = packh2(s[2 * kb][0], s[2 * kb][1]);
            uint32_t a1 = packh2(s[2 * kb][2], s[2 * kb][3]);
            uint32_t a2 = packh2(s[2 * kb + 1][0], s[2 * kb + 1][1]);
            uint32_t a3 = packh2(s[2 * kb + 1][2], s[2 * kb + 1][3]);
            uint32_t rowoff = (uint32_t)(kb * 16 * SPVH * 2);
#pragma unroll
            for (int dp = 0; dp < 4; dp++) {
                uint32_t b0, b1, b2, b3;
                asm volatile(
                    "ldmatrix.sync.aligned.m8n8.x4.trans.shared.b16 "
                    "{%0,%1,%2,%3}, [%4];"
                    : "=r"(b0), "=r"(b1), "=r"(b2), "=r"(b3)
                    : "r"(vb + rowoff + dp * 32));
                mma_f16(o[2 * dp], a0, a1, a2, a3, b0, b1);
                mma_f16(o[2 * dp + 1], a0, a1, a2, a3, b2, b3);
            }
        }
    }

    float qm0 = qmask[(size_t)b_ * Ss + r0];
    float qm1 = qmask[(size_t)b_ * Ss + r1];
    float sc0 = qm0 / l0, sc1 = qm1 / l1;
    float* ob0 = out + ((size_t)b_ * Ss + r0) * DM + h * 64;
    float* ob1 = out + ((size_t)b_ * Ss + r1) * DM + h * 64;
#pragma unroll
    for (int nd = 0; nd < 8; nd++) {
        *(float2*)&ob0[nd * 8 + 2 * t] =
            make_float2(o[nd][0] * sc0, o[nd][1] * sc0);
        *(float2*)&ob1[nd * 8 + 2 * t] =
            make_float2(o[nd][2] * sc1, o[nd][3] * sc1);
    }
}

extern "C" void kernel_launch(void* const* d_in, const int* in_sizes, int n_in,
                              void* d_out, int out_size)
{
    const float* q     = (const float*)d_in[0];
    const float* k     = (const float*)d_in[1];
    const float* v     = (const float*)d_in[2];
    const float* vmask = (const float*)d_in[3];
    const float* qmask = (const float*)d_in[4];
    const float* Wq    = (const float*)d_in[5];
    const float* Wk    = (const float*)d_in[6];
    const float* Wv    = (const float*)d_in[7];
    float* out = (float*)d_out;

    int proj_smem = PROJ_SMEM_FLOATS * sizeof(float);
    cudaFuncSetAttribute(proj_mma_kernel,
                         cudaFuncAttributeMaxDynamicSharedMemorySize, proj_smem);
    dim3 pg(DM / 128, (Bb * Ss) / 128, 3);
    proj_mma_kernel<<<pg, 256, proj_smem>>>(q, k, v, Wq, Wk, Wv);

    int fa_smem = FA_SMEM_FLOATS * sizeof(float);
    cudaFuncSetAttribute(fa_mma_kernel,
                         cudaFuncAttributeMaxDynamicSharedMemorySize, fa_smem);
    dim3 fg(Ss / 128, Bb * Hh);
    fa_mma_kernel<<<fg, 256, fa_smem>>>(vmask, qmask, out);
}

// round 9
// speedup vs baseline: 3.5801x; 1.0135x over previous
#include <cuda_runtime.h>
#include <cuda_fp16.h>
#include <cstdint>

#define Bb 4
#define Ss 2048
#define DM 1024
#define Hh 16
#define Dh 64
#define NEG_BIG 1e10f
// base-2 domain constants
#define SCALE2 0.18033688011112042f   /* 0.125 * log2(e) */
#define BIG2   1.4426950408889634e10f /* NEG_BIG * log2(e) */

// Scratch (allocation-free rule: __device__ globals).
__device__ float  g_qw[Bb * Hh * Ss * Dh];   // k-interleaved within 8-blocks
__device__ float  g_kw[Bb * Hh * Ss * Dh];   // k-interleaved within 8-blocks
__device__ __half g_vh[Bb * Hh * Ss * Dh];   // fp16 V

__device__ __forceinline__ uint32_t smem_u32(const void* p) {
    uint32_t a;
    asm("{ .reg .u64 t; cvta.to.shared.u64 t, %1; cvt.u32.u64 %0, t; }"
        : "=r"(a) : "l"(p));
    return a;
}
__device__ __forceinline__ uint32_t f2tf32(float f) {
    uint32_t r;
    asm("cvt.rna.tf32.f32 %0, %1;" : "=r"(r) : "f"(f));
    return r;
}
__device__ __forceinline__ float ex2f(float x) {
    float r;
    asm("ex2.approx.ftz.f32 %0, %1;" : "=f"(r) : "f"(x));
    return r;
}
__device__ __forceinline__ uint32_t packh2(float lo, float hi) {
    uint32_t r;
    asm("cvt.rn.f16x2.f32 %0, %1, %2;" : "=r"(r) : "f"(hi), "f"(lo));
    return r;
}
__device__ __forceinline__ void cp_async16(uint32_t dst, const void* src) {
    asm volatile("cp.async.cg.shared.global [%0], [%1], 16;"
                 :: "r"(dst), "l"(src) : "memory");
}
__device__ __forceinline__ void mma_tf32(float* d, const uint32_t* a,
                                         const uint32_t* b) {
    asm volatile(
        "mma.sync.aligned.m16n8k8.row.col.f32.tf32.tf32.f32 "
        "{%0,%1,%2,%3}, {%4,%5,%6,%7}, {%8,%9}, {%0,%1,%2,%3};"
        : "+f"(d[0]), "+f"(d[1]), "+f"(d[2]), "+f"(d[3])
        : "r"(a[0]), "r"(a[1]), "r"(a[2]), "r"(a[3]), "r"(b[0]), "r"(b[1]));
}
__device__ __forceinline__ void mma_f16(float* d, uint32_t a0, uint32_t a1,
                                        uint32_t a2, uint32_t a3,
                                        uint32_t b0, uint32_t b1) {
    asm volatile(
        "mma.sync.aligned.m16n8k16.row.col.f32.f16.f16.f32 "
        "{%0,%1,%2,%3}, {%4,%5,%6,%7}, {%8,%9}, {%0,%1,%2,%3};"
        : "+f"(d[0]), "+f"(d[1]), "+f"(d[2]), "+f"(d[3])
        : "r"(a0), "r"(a1), "r"(a2), "r"(a3), "r"(b0), "r"(b1));
}

// ---------------------------------------------------------------------------
// Projection GEMM: raw fp32 X [M,K] and W [K,N], cvt->tf32 in-register.
// CTA 128x128, BK=32, 3-stage cp.async ring, one barrier per stage.
// Epilogue: stage full 128x128 C into smem [128][132] (perm+round at STS),
// then coalesced float4 sweep out.
// ---------------------------------------------------------------------------
#define BK2 32
#define PA 36
#define PB 136
#define PC 132                   /* 128 cols + 4 pad */
#define A_ST (128 * PA)          /* 4608 floats */
#define B_ST (BK2 * PB)          /* 4352 floats */
#define PROJ_SMEM_FLOATS (3 * (A_ST + B_ST))   /* 26880 >= 128*132=16896 */

__global__ __launch_bounds__(256, 2)
void proj_mma_kernel(const float* __restrict__ qin,
                     const float* __restrict__ kin,
                     const float* __restrict__ vin,
                     const float* __restrict__ Wq,
                     const float* __restrict__ Wk,
                     const float* __restrict__ Wv)
{
    extern __shared__ float psm[];
    const int z = blockIdx.z;
    const float* X = (z == 0) ? qin : (z == 1) ? kin : vin;
    const float* W = (z == 0) ? Wq : (z == 1) ? Wk : Wv;
    float* O = (z == 0) ? g_qw : g_kw;

    const int m0 = blockIdx.y * 128;
    const int n0 = blockIdx.x * 128;
    const int tid = threadIdx.x;
    const int lane = tid & 31;
    const int warp = tid >> 5;
    const int wm = (warp >> 2) * 64;
    const int wn = (warp & 3) * 32;
    const int g = lane >> 2, t = lane & 3;

    uint32_t uA[3], uB[3];
#pragma unroll
    for (int i = 0; i < 3; i++) {
        uA[i] = smem_u32(psm + i * (A_ST + B_ST));
        uB[i] = smem_u32(psm + i * (A_ST + B_ST) + A_ST);
    }

    float acc[4][4][4];
#pragma unroll
    for (int i = 0; i < 4; i++)
#pragma unroll
        for (int j = 0; j < 4; j++)
#pragma unroll
            for (int c = 0; c < 4; c++) acc[i][j][c] = 0.f;

    auto issue = [&](int kt) {
        const int st = kt % 3;
        const int k0 = kt * BK2;
#pragma unroll
        for (int i = 0; i < 4; i++) {
            int idx = tid + i * 256;
            int row = idx >> 3, c4 = (idx & 7) * 4;
            cp_async16(uA[st] + (uint32_t)(row * PA + c4) * 4,
                       &X[(size_t)(m0 + row) * DM + k0 + c4]);
        }
#pragma unroll
        for (int i = 0; i < 4; i++) {
            int idx = tid + i * 256;
            int row = idx >> 5, c4 = (idx & 31) * 4;
            cp_async16(uB[st] + (uint32_t)(row * PB + c4) * 4,
                       &W[(size_t)(k0 + row) * DM + n0 + c4]);
        }
        asm volatile("cp.async.commit_group;" ::: "memory");
    };

    issue(0);
    issue(1);

    const int NSTAGE = DM / BK2;   // 32
    for (int kt = 0; kt < NSTAGE; kt++) {
        if (kt + 2 < NSTAGE)
            asm volatile("cp.async.wait_group 1;" ::: "memory");
        else
            asm volatile("cp.async.wait_group 0;" ::: "memory");
        __syncthreads();
        if (kt + 2 < NSTAGE) issue(kt + 2);

        const int st = kt % 3;
        const float* as = psm + st * (A_ST + B_ST);
        const float* bs = as + A_ST;
#pragma unroll
        for (int ks = 0; ks < 4; ks++) {
            uint32_t a[4][4];
#pragma unroll
            for (int mf = 0; mf < 4; mf++) {
                const float* p = &as[(wm + mf * 16 + g) * PA + ks * 8 + t];
                a[mf][0] = f2tf32(p[0]);
                a[mf][1] = f2tf32(p[8 * PA]);
                a[mf][2] = f2tf32(p[4]);
                a[mf][3] = f2tf32(p[8 * PA + 4]);
            }
            uint32_t bb[4][2];
#pragma unroll
            for (int nf = 0; nf < 4; nf++) {
                const float* p = &bs[(ks * 8 + t) * PB + wn + nf * 8 + g];
                bb[nf][0] = f2tf32(p[0]);
                bb[nf][1] = f2tf32(p[4 * PB]);
            }
#pragma unroll
            for (int mf = 0; mf < 4; mf++)
#pragma unroll
                for (int nf = 0; nf < 4; nf++)
                    mma_tf32(acc[mf][nf], a[mf], bb[nf]);
        }
    }

    // ---- Epilogue: stage full tile into smem, coalesced sweep out ----
    __syncthreads();   // ring drained (wait_group 0 above); safe to reuse psm
    float* ct = psm;   // [128][PC=132]
    const int j0 = 2 * t;
    const int p0 = (j0 < 4) ? 2 * j0 : 2 * j0 - 7;  // k-interleave perm

#pragma unroll
    for (int mf = 0; mf < 4; mf++) {
#pragma unroll
        for (int nf = 0; nf < 4; nf++) {
            int ml = wm + mf * 16 + g;
            int nb = wn + nf * 8;
            if (z < 2) {
                ct[ml * PC + nb + p0] =
                    __uint_as_float(f2tf32(acc[mf][nf][0]));
                ct[ml * PC + nb + p0 + 2] =
                    __uint_as_float(f2tf32(acc[mf][nf][1]));
                ct[(ml + 8) * PC + nb + p0] =
                    __uint_as_float(f2tf32(acc[mf][nf][2]));
                ct[(ml + 8) * PC + nb + p0 + 2] =
                    __uint_as_float(f2tf32(acc[mf][nf][3]));
            } else {
                ct[ml * PC + nb + j0]           = acc[mf][nf][0];
                ct[ml * PC + nb + j0 + 1]       = acc[mf][nf][1];
                ct[(ml + 8) * PC + nb + j0]     = acc[mf][nf][2];
                ct[(ml + 8) * PC + nb + j0 + 1] = acc[mf][nf][3];
            }
        }
    }
    __syncthreads();

    // Linear sweep: 128 rows x 128 floats = 4096 float4 chunks, 16/thread.
#pragma unroll
    for (int i = 0; i < 16; i++) {
        int idx = tid + i * 256;
        int row = idx >> 5;            // 32 chunks per 128-float row
        int c4 = (idx & 31) * 4;
        float4 val = *(const float4*)&ct[row * PC + c4];
        int m = m0 + row;
        int n = n0 + c4;
        int b_ = m >> 11, s = m & 2047, h = n >> 6, d = n & 63;
        size_t base = ((((size_t)b_ * Hh + h) * Ss) + s) * Dh + d;
        if (z < 2) {
            *(float4*)&O[base] = val;
        } else {
            __half2 h01 = __floats2half2_rn(val.x, val.y);
            __half2 h23 = __floats2half2_rn(val.z, val.w);
            uint2 pk = make_uint2(*(uint32_t*)&h01, *(uint32_t*)&h23);
            *(uint2*)&g_vh[base] = pk;
        }
    }
}

// ---------------------------------------------------------------------------
// Flash attention (unchanged from R7): QK^T tf32 mma, PV fp16 m16n8k16.
// ---------------------------------------------------------------------------
#define SPK 68      /* K/Q smem stride in floats  */
#define SPVH 72     /* V smem stride in halves    */
#define FA_SMEM_FLOATS (8704 + 8704 + 4608 + 128)

__global__ __launch_bounds__(256, 2)
void fa_mma_kernel(const float* __restrict__ vmask,
                   const float* __restrict__ qmask, float* __restrict__ out)
{
    extern __shared__ float sm[];
    float*  Qs   = sm;                    // 8704
    float*  Kb0  = sm + 8704;             // 4352
    float*  Kb1  = sm + 13056;            // 4352
    __half* Vh0  = (__half*)(sm + 17408); // 64*72 halves = 2304 floats
    __half* Vh1  = (__half*)(sm + 19712);
    float*  vm0b = sm + 22016;
    float*  vm1b = sm + 22080;

    const int qt = (int)gridDim.x - 1 - (int)blockIdx.x;  // heavy tiles first
    const int bh = blockIdx.y;
    const int b_ = bh >> 4, h = bh & 15;
    const int tid = threadIdx.x, lane = tid & 31, wid = tid >> 5;
    const int g = lane >> 2, t = lane & 3;

    const uint32_t uQ = smem_u32(Qs);
    const uint32_t uK[2] = { smem_u32(Kb0), smem_u32(Kb1) };
    const uint32_t uV[2] = { smem_u32(Vh0), smem_u32(Vh1) };
    const uint32_t uM[2] = { smem_u32(vm0b), smem_u32(vm1b) };

    const float*  Kg = &g_kw[(size_t)bh * Ss * Dh];
    const __half* Vg = &g_vh[(size_t)bh * Ss * Dh];

    auto issue = [&](int jt, int bsel) {
        const int lrow = tid >> 2;
        const int lf = (tid & 3) * 16;
#pragma unroll
        for (int i = 0; i < 4; i++) {
            int c = lf + i * 4;
            cp_async16(uK[bsel] + (uint32_t)(lrow * SPK + c) * 4,
                       Kg + (size_t)(jt * 64 + lrow) * Dh + c);
        }
#pragma unroll
        for (int i = 0; i < 2; i++) {
            int idx = tid + i * 256;
            int row = idx >> 3, c16 = idx & 7;
            cp_async16(uV[bsel] + (uint32_t)(row * SPVH * 2 + c16 * 16),
                       Vg + (size_t)(jt * 64 + row) * Dh + c16 * 8);
        }
        if (tid < 16)
            cp_async16(uM[bsel] + tid * 16,
                       vmask + (size_t)b_ * Ss + jt * 64 + tid * 4);
        asm volatile("cp.async.commit_group;" ::: "memory");
    };

    issue(0, 0);

    {
        const float* Qg = &g_qw[((size_t)bh * Ss + qt * 128) * Dh];
#pragma unroll
        for (int i = 0; i < 8; i++) {
            int idx = tid + i * 256;
            int row = idx >> 4, c16 = idx & 15;
            cp_async16(uQ + (uint32_t)(row * SPK + c16 * 4) * 4,
                       Qg + (size_t)row * Dh + c16 * 4);
        }
        asm volatile("cp.async.commit_group;" ::: "memory");
    }

    const float NEG_INF = -__int_as_float(0x7f800000);
    float m0 = NEG_INF, m1 = NEG_INF, l0 = 0.f, l1 = 0.f;
    float o[8][4];
#pragma unroll
    for (int i = 0; i < 8; i++)
#pragma unroll
        for (int j = 0; j < 4; j++) o[i][j] = 0.f;

    const int r0 = qt * 128 + wid * 16 + g;
    const int r1 = r0 + 8;
    const int wr = wid * 16;
    const uint32_t vtile_off =
        (uint32_t)(((lane & 7) + ((lane >> 3) & 1) * 8) * SPVH * 2 +
                   (lane >> 4) * 16);

    const int nt = 2 * qt + 2;
    for (int jt = 0; jt < nt; jt++) {
        const int bsel = jt & 1;
        asm volatile("cp.async.wait_group 0;" ::: "memory");
        __syncthreads();
        if (jt + 1 < nt) issue(jt + 1, bsel ^ 1);

        const float* ksm = bsel ? Kb1 : Kb0;
        const float* vmp = bsel ? vm1b : vm0b;
        const uint32_t vb = uV[bsel] + vtile_off;

        float s[8][4];
#pragma unroll
        for (int n = 0; n < 8; n++)
#pragma unroll
            for (int j = 0; j < 4; j++) s[n][j] = 0.f;
#pragma unroll
        for (int ks = 0; ks < 8; ks++) {
            float2 a0p = *(const float2*)&Qs[(wr + g) * SPK + ks * 8 + 2 * t];
            float2 a1p = *(const float2*)&Qs[(wr + g + 8) * SPK + ks * 8 + 2 * t];
            uint32_t a[4] = { __float_as_uint(a0p.x), __float_as_uint(a1p.x),
                              __float_as_uint(a0p.y), __float_as_uint(a1p.y) };
#pragma unroll
            for (int n = 0; n < 8; n++) {
                float2 bp = *(const float2*)&ksm[(n * 8 + g) * SPK + ks * 8 + 2 * t];
                uint32_t bb[2] = { __float_as_uint(bp.x), __float_as_uint(bp.y) };
                mma_tf32(s[n], a, bb);
            }
        }

        const bool cneed = (jt * 64 + 63) > (qt * 128 + wid * 16);
        float rm0 = NEG_INF, rm1 = NEG_INF;
#pragma unroll
        for (int n = 0; n < 8; n++) {
            float vmv0 = vmp[n * 8 + 2 * t];
            float vmv1 = vmp[n * 8 + 2 * t + 1];
            int c0 = jt * 64 + n * 8 + 2 * t;
            float s0 = s[n][0] * SCALE2 - (1.f - vmv0) * BIG2;
            float s1 = s[n][1] * SCALE2 - (1.f - vmv1) * BIG2;
            float s2 = s[n][2] * SCALE2 - (1.f - vmv0) * BIG2;
            float s3 = s[n][3] * SCALE2 - (1.f - vmv1) * BIG2;
            if (cneed) {
                if (c0 > r0) s0 -= BIG2;
                if (c0 + 1 > r0) s1 -= BIG2;
                if (c0 > r1) s2 -= BIG2;
                if (c0 + 1 > r1) s3 -= BIG2;
            }
            s[n][0] = s0; s[n][1] = s1; s[n][2] = s2; s[n][3] = s3;
            rm0 = fmaxf(rm0, fmaxf(s0, s1));
            rm1 = fmaxf(rm1, fmaxf(s2, s3));
        }
        rm0 = fmaxf(rm0, __shfl_xor_sync(0xffffffffu, rm0, 1));
        rm0 = fmaxf(rm0, __shfl_xor_sync(0xffffffffu, rm0, 2));
        rm1 = fmaxf(rm1, __shfl_xor_sync(0xffffffffu, rm1, 1));
        rm1 = fmaxf(rm1, __shfl_xor_sync(0xffffffffu, rm1, 2));

        float mn0 = fmaxf(m0, rm0), mn1 = fmaxf(m1, rm1);
        float cr0 = ex2f(m0 - mn0), cr1 = ex2f(m1 - mn1);
        float rs0 = 0.f, rs1 = 0.f;
#pragma unroll
        for (int n = 0; n < 8; n++) {
            s[n][0] = ex2f(s[n][0] - mn0);
            s[n][1] = ex2f(s[n][1] - mn0);
            s[n][2] = ex2f(s[n][2] - mn1);
            s[n][3] = ex2f(s[n][3] - mn1);
            rs0 += s[n][0] + s[n][1];
            rs1 += s[n][2] + s[n][3];
        }
        rs0 += __shfl_xor_sync(0xffffffffu, rs0, 1);
        rs0 += __shfl_xor_sync(0xffffffffu, rs0, 2);
        rs1 += __shfl_xor_sync(0xffffffffu, rs1, 1);
        rs1 += __shfl_xor_sync(0xffffffffu, rs1, 2);
        l0 = l0 * cr0 + rs0;
        l1 = l1 * cr1 + rs1;
        m0 = mn0; m1 = mn1;
#pragma unroll
        for (int nd = 0; nd < 8; nd++) {
            o[nd][0] *= cr0; o[nd][1] *= cr0;
            o[nd][2] *= cr1; o[nd][3] *= cr1;
        }

#pragma unroll
        for (int kb = 0; kb < 4; kb++) {
            uint32_t a0 = packh2(s[2 * kb][0], s[2 * kb][1]);
            uint32_t a1 = packh2(s[2 * kb][2], s[2 * kb][3]);
            uint32_t a2 = packh2(s[2 * kb + 1][0], s[2 * kb + 1][1]);
            uint32_t a3 = packh2(s[2 * kb + 1][2], s[2 * kb + 1][3]);
            uint32_t rowoff = (uint32_t)(kb * 16 * SPVH * 2);
#pragma unroll
            for (int dp = 0; dp < 4; dp++) {
                uint32_t b0, b1, b2, b3;
                asm volatile(
                    "ldmatrix.sync.aligned.m8n8.x4.trans.shared.b16 "
                    "{%0,%1,%2,%3}, [%4];"
                    : "=r"(b0), "=r"(b1), "=r"(b2), "=r"(b3)
                    : "r"(vb + rowoff + dp * 32));
                mma_f16(o[2 * dp], a0, a1, a2, a3, b0, b1);
                mma_f16(o[2 * dp + 1], a0, a1, a2, a3, b2, b3);
            }
        }
    }

    float qm0 = qmask[(size_t)b_ * Ss + r0];
    float qm1 = qmask[(size_t)b_ * Ss + r1];
    float sc0 = qm0 / l0, sc1 = qm1 / l1;
    float* ob0 = out + ((size_t)b_ * Ss + r0) * DM + h * 64;
    float* ob1 = out + ((size_t)b_ * Ss + r1) * DM + h * 64;
#pragma unroll
    for (int nd = 0; nd < 8; nd++) {
        *(float2*)&ob0[nd * 8 + 2 * t] =
            make_float2(o[nd][0] * sc0, o[nd][1] * sc0);
        *(float2*)&ob1[nd * 8 + 2 * t] =
            make_float2(o[nd][2] * sc1, o[nd][3] * sc1);
    }
}

extern "C" void kernel_launch(void* const* d_in, const int* in_sizes, int n_in,
                              void* d_out, int out_size)
{
    const float* q     = (const float*)d_in[0];
    const float* k     = (const float*)d_in[1];
    const float* v     = (const float*)d_in[2];
    const float* vmask = (const float*)d_in[3];
    const float* qmask = (const float*)d_in[4];
    const float* Wq    = (const float*)d_in[5];
    const float* Wk    = (const float*)d_in[6];
    const float* Wv    = (const float*)d_in[7];
    float* out = (float*)d_out;

    int proj_smem = PROJ_SMEM_FLOATS * sizeof(float);
    cudaFuncSetAttribute(proj_mma_kernel,
                         cudaFuncAttributeMaxDynamicSharedMemorySize, proj_smem);
    dim3 pg(DM / 128, (Bb * Ss) / 128, 3);
    proj_mma_kernel<<<pg, 256, proj_smem>>>(q, k, v, Wq, Wk, Wv);

    int fa_smem = FA_SMEM_FLOATS * sizeof(float);
    cudaFuncSetAttribute(fa_mma_kernel,
                         cudaFuncAttributeMaxDynamicSharedMemorySize, fa_smem);
    dim3 fg(Ss / 128, Bb * Hh);
    fa_mma_kernel<<<fg, 256, fa_smem>>>(vmask, qmask, out);
}

// round 10
// speedup vs baseline: 4.3456x; 1.2138x over previous
#include <cuda_runtime.h>
#include <cuda_fp16.h>
#include <cstdint>

#define Bb 4
#define Ss 2048
#define DM 1024
#define Hh 16
#define Dh 64
#define NEG_BIG 1e10f
// base-2 domain constants
#define SCALE2 0.18033688011112042f   /* 0.125 * log2(e) */
#define BIG2   1.4426950408889634e10f /* NEG_BIG * log2(e) */

// Scratch (allocation-free rule: __device__ globals).
__device__ float  g_qw[Bb * Hh * Ss * Dh];   // 16-wide k-interleaved
__device__ float  g_kw[Bb * Hh * Ss * Dh];   // 16-wide k-interleaved
__device__ __half g_vh[Bb * Hh * Ss * Dh];   // fp16 V

__device__ __forceinline__ uint32_t smem_u32(const void* p) {
    uint32_t a;
    asm("{ .reg .u64 t; cvta.to.shared.u64 t, %1; cvt.u32.u64 %0, t; }"
        : "=r"(a) : "l"(p));
    return a;
}
__device__ __forceinline__ uint32_t f2tf32(float f) {
    uint32_t r;
    asm("cvt.rna.tf32.f32 %0, %1;" : "=r"(r) : "f"(f));
    return r;
}
__device__ __forceinline__ float ex2f(float x) {
    float r;
    asm("ex2.approx.ftz.f32 %0, %1;" : "=f"(r) : "f"(x));
    return r;
}
__device__ __forceinline__ uint32_t packh2(float lo, float hi) {
    uint32_t r;
    asm("cvt.rn.f16x2.f32 %0, %1, %2;" : "=r"(r) : "f"(hi), "f"(lo));
    return r;
}
__device__ __forceinline__ void cp_async16(uint32_t dst, const void* src) {
    asm volatile("cp.async.cg.shared.global [%0], [%1], 16;"
                 :: "r"(dst), "l"(src) : "memory");
}
__device__ __forceinline__ void mma_tf32(float* d, const uint32_t* a,
                                         const uint32_t* b) {
    asm volatile(
        "mma.sync.aligned.m16n8k8.row.col.f32.tf32.tf32.f32 "
        "{%0,%1,%2,%3}, {%4,%5,%6,%7}, {%8,%9}, {%0,%1,%2,%3};"
        : "+f"(d[0]), "+f"(d[1]), "+f"(d[2]), "+f"(d[3])
        : "r"(a[0]), "r"(a[1]), "r"(a[2]), "r"(a[3]), "r"(b[0]), "r"(b[1]));
}
__device__ __forceinline__ void mma_tf32r(float* d, uint32_t a0, uint32_t a1,
                                          uint32_t a2, uint32_t a3,
                                          uint32_t b0, uint32_t b1) {
    asm volatile(
        "mma.sync.aligned.m16n8k8.row.col.f32.tf32.tf32.f32 "
        "{%0,%1,%2,%3}, {%4,%5,%6,%7}, {%8,%9}, {%0,%1,%2,%3};"
        : "+f"(d[0]), "+f"(d[1]), "+f"(d[2]), "+f"(d[3])
        : "r"(a0), "r"(a1), "r"(a2), "r"(a3), "r"(b0), "r"(b1));
}
__device__ __forceinline__ void mma_f16(float* d, uint32_t a0, uint32_t a1,
                                        uint32_t a2, uint32_t a3,
                                        uint32_t b0, uint32_t b1) {
    asm volatile(
        "mma.sync.aligned.m16n8k16.row.col.f32.f16.f16.f32 "
        "{%0,%1,%2,%3}, {%4,%5,%6,%7}, {%8,%9}, {%0,%1,%2,%3};"
        : "+f"(d[0]), "+f"(d[1]), "+f"(d[2]), "+f"(d[3])
        : "r"(a0), "r"(a1), "r"(a2), "r"(a3), "r"(b0), "r"(b1));
}

// ---------------------------------------------------------------------------
// Projection GEMM (as R9): fp32 in, cvt->tf32 in-register, BK=32, 3-stage.
// Epilogue: Q/K now stored with 16-wide k-interleave sigma(j)=4*(j&3)+(j>>2);
// V as fp16. Staged through smem, coalesced sweep out.
// ---------------------------------------------------------------------------
#define BK2 32
#define PA 36
#define PB 136
#define PC 132
#define A_ST (128 * PA)
#define B_ST (BK2 * PB)
#define PROJ_SMEM_FLOATS (3 * (A_ST + B_ST))

__global__ __launch_bounds__(256, 2)
void proj_mma_kernel(const float* __restrict__ qin,
                     const float* __restrict__ kin,
                     const float* __restrict__ vin,
                     const float* __restrict__ Wq,
                     const float* __restrict__ Wk,
                     const float* __restrict__ Wv)
{
    extern __shared__ float psm[];
    const int z = blockIdx.z;
    const float* X = (z == 0) ? qin : (z == 1) ? kin : vin;
    const float* W = (z == 0) ? Wq : (z == 1) ? Wk : Wv;
    float* O = (z == 0) ? g_qw : g_kw;

    const int m0 = blockIdx.y * 128;
    const int n0 = blockIdx.x * 128;
    const int tid = threadIdx.x;
    const int lane = tid & 31;
    const int warp = tid >> 5;
    const int wm = (warp >> 2) * 64;
    const int wn = (warp & 3) * 32;
    const int g = lane >> 2, t = lane & 3;

    uint32_t uA[3], uB[3];
#pragma unroll
    for (int i = 0; i < 3; i++) {
        uA[i] = smem_u32(psm + i * (A_ST + B_ST));
        uB[i] = smem_u32(psm + i * (A_ST + B_ST) + A_ST);
    }

    float acc[4][4][4];
#pragma unroll
    for (int i = 0; i < 4; i++)
#pragma unroll
        for (int j = 0; j < 4; j++)
#pragma unroll
            for (int c = 0; c < 4; c++) acc[i][j][c] = 0.f;

    auto issue = [&](int kt) {
        const int st = kt % 3;
        const int k0 = kt * BK2;
#pragma unroll
        for (int i = 0; i < 4; i++) {
            int idx = tid + i * 256;
            int row = idx >> 3, c4 = (idx & 7) * 4;
            cp_async16(uA[st] + (uint32_t)(row * PA + c4) * 4,
                       &X[(size_t)(m0 + row) * DM + k0 + c4]);
        }
#pragma unroll
        for (int i = 0; i < 4; i++) {
            int idx = tid + i * 256;
            int row = idx >> 5, c4 = (idx & 31) * 4;
            cp_async16(uB[st] + (uint32_t)(row * PB + c4) * 4,
                       &W[(size_t)(k0 + row) * DM + n0 + c4]);
        }
        asm volatile("cp.async.commit_group;" ::: "memory");
    };

    issue(0);
    issue(1);

    const int NSTAGE = DM / BK2;   // 32
    for (int kt = 0; kt < NSTAGE; kt++) {
        if (kt + 2 < NSTAGE)
            asm volatile("cp.async.wait_group 1;" ::: "memory");
        else
            asm volatile("cp.async.wait_group 0;" ::: "memory");
        __syncthreads();
        if (kt + 2 < NSTAGE) issue(kt + 2);

        const int st = kt % 3;
        const float* as = psm + st * (A_ST + B_ST);
        const float* bs = as + A_ST;
#pragma unroll
        for (int ks = 0; ks < 4; ks++) {
            uint32_t a[4][4];
#pragma unroll
            for (int mf = 0; mf < 4; mf++) {
                const float* p = &as[(wm + mf * 16 + g) * PA + ks * 8 + t];
                a[mf][0] = f2tf32(p[0]);
                a[mf][1] = f2tf32(p[8 * PA]);
                a[mf][2] = f2tf32(p[4]);
                a[mf][3] = f2tf32(p[8 * PA + 4]);
            }
            uint32_t bb[4][2];
#pragma unroll
            for (int nf = 0; nf < 4; nf++) {
                const float* p = &bs[(ks * 8 + t) * PB + wn + nf * 8 + g];
                bb[nf][0] = f2tf32(p[0]);
                bb[nf][1] = f2tf32(p[4 * PB]);
            }
#pragma unroll
            for (int mf = 0; mf < 4; mf++)
#pragma unroll
                for (int nf = 0; nf < 4; nf++)
                    mma_tf32(acc[mf][nf], a[mf], bb[nf]);
        }
    }

    // ---- Epilogue: stage full tile into smem, coalesced sweep out ----
    __syncthreads();
    float* ct = psm;   // [128][PC=132]
    const int j0 = 2 * t;

#pragma unroll
    for (int mf = 0; mf < 4; mf++) {
#pragma unroll
        for (int nf = 0; nf < 4; nf++) {
            int ml = wm + mf * 16 + g;
            int nb = wn + nf * 8;
            if (z < 2) {
                // 16-wide interleave: j within 16-block, sigma(j)=4*(j&3)+(j>>2)
                int jb = (nb & 8) + j0;
                int c16 = nb & ~15;
                int d0 = 4 * (jb & 3) + (jb >> 2);
                ct[ml * PC + c16 + d0] =
                    __uint_as_float(f2tf32(acc[mf][nf][0]));
                ct[ml * PC + c16 + d0 + 4] =
                    __uint_as_float(f2tf32(acc[mf][nf][1]));
                ct[(ml + 8) * PC + c16 + d0] =
                    __uint_as_float(f2tf32(acc[mf][nf][2]));
                ct[(ml + 8) * PC + c16 + d0 + 4] =
                    __uint_as_float(f2tf32(acc[mf][nf][3]));
            } else {
                ct[ml * PC + nb + j0]           = acc[mf][nf][0];
                ct[ml * PC + nb + j0 + 1]       = acc[mf][nf][1];
                ct[(ml + 8) * PC + nb + j0]     = acc[mf][nf][2];
                ct[(ml + 8) * PC + nb + j0 + 1] = acc[mf][nf][3];
            }
        }
    }
    __syncthreads();

#pragma unroll
    for (int i = 0; i < 16; i++) {
        int idx = tid + i * 256;
        int row = idx >> 5;
        int c4 = (idx & 31) * 4;
        float4 val = *(const float4*)&ct[row * PC + c4];
        int m = m0 + row;
        int n = n0 + c4;
        int b_ = m >> 11, s = m & 2047, h = n >> 6, d = n & 63;
        size_t base = ((((size_t)b_ * Hh + h) * Ss) + s) * Dh + d;
        if (z < 2) {
            *(float4*)&O[base] = val;
        } else {
            __half2 h01 = __floats2half2_rn(val.x, val.y);
            __half2 h23 = __floats2half2_rn(val.z, val.w);
            uint2 pk = make_uint2(*(uint32_t*)&h01, *(uint32_t*)&h23);
            *(uint2*)&g_vh[base] = pk;
        }
    }
}

// ---------------------------------------------------------------------------
// Flash attention v2: 128 threads (4 warps x 32 q-rows), 256 regs/thread.
// Q frags register-cached from gmem; K frags via LDS.128 (16-interleave,
// SPK=80 conflict-free); every K/V operand load feeds 2 row-blocks.
// ---------------------------------------------------------------------------
#define SPK 80      /* K smem stride in floats (80 % 32 == 16) */
#define SPVH 72     /* V smem stride in halves */
#define K_ST (64 * SPK)            /* 5120 floats per K buffer */
#define FA_SMEM_FLOATS (2 * K_ST + 2 * 2304 + 128)   /* 14976 fl = 59.9KB */

__global__ __launch_bounds__(128, 2)
void fa_mma_kernel(const float* __restrict__ vmask,
                   const float* __restrict__ qmask, float* __restrict__ out)
{
    extern __shared__ float sm[];
    float*  Kb0  = sm;                       // 5120
    float*  Kb1  = sm + K_ST;                // 5120
    __half* Vh0  = (__half*)(sm + 2 * K_ST); // 2304 fl
    __half* Vh1  = (__half*)(sm + 2 * K_ST + 2304);
    float*  vm0b = sm + 2 * K_ST + 4608;
    float*  vm1b = vm0b + 64;

    const int qt = (int)gridDim.x - 1 - (int)blockIdx.x;  // heavy tiles first
    const int bh = blockIdx.y;
    const int b_ = bh >> 4, h = bh & 15;
    const int tid = threadIdx.x, lane = tid & 31, wid = tid >> 5;
    const int g = lane >> 2, t = lane & 3;
    const int wr = wid * 32;

    const uint32_t uK[2] = { smem_u32(Kb0), smem_u32(Kb1) };
    const uint32_t uV[2] = { smem_u32(Vh0), smem_u32(Vh1) };
    const uint32_t uM[2] = { smem_u32(vm0b), smem_u32(vm1b) };

    const float*  Kg = &g_kw[(size_t)bh * Ss * Dh];
    const __half* Vg = &g_vh[(size_t)bh * Ss * Dh];

    auto issue = [&](int jt, int bsel) {
        // K: 64 rows x 64 fl = 1024 16B-chunks, 8 per thread
#pragma unroll
        for (int i = 0; i < 8; i++) {
            int idx = tid + i * 128;
            int row = idx >> 4, c16 = idx & 15;
            cp_async16(uK[bsel] + (uint32_t)(row * SPK + c16 * 4) * 4,
                       Kg + (size_t)(jt * 64 + row) * Dh + c16 * 4);
        }
        // V: 64 rows x 128B = 512 chunks, 4 per thread
#pragma unroll
        for (int i = 0; i < 4; i++) {
            int idx = tid + i * 128;
            int row = idx >> 3, c16 = idx & 7;
            cp_async16(uV[bsel] + (uint32_t)(row * SPVH * 2 + c16 * 16),
                       Vg + (size_t)(jt * 64 + row) * Dh + c16 * 8);
        }
        if (tid < 16)
            cp_async16(uM[bsel] + tid * 16,
                       vmask + (size_t)b_ * Ss + jt * 64 + tid * 4);
        asm volatile("cp.async.commit_group;" ::: "memory");
    };

    issue(0, 0);

    // Q fragments register-cached for the whole kv loop.
    // qlo[b2][P] = row wr+16*b2+g, floats 16P+4t.. ; qhi = row +8.
    uint4 qlo[2][4], qhi[2][4];
    {
        const float* Qg = &g_qw[((size_t)bh * Ss + qt * 128) * Dh];
#pragma unroll
        for (int b2 = 0; b2 < 2; b2++)
#pragma unroll
            for (int P = 0; P < 4; P++) {
                qlo[b2][P] = *(const uint4*)&Qg[(size_t)(wr + 16 * b2 + g) * Dh
                                               + 16 * P + 4 * t];
                qhi[b2][P] = *(const uint4*)&Qg[(size_t)(wr + 16 * b2 + g + 8) * Dh
                                               + 16 * P + 4 * t];
            }
    }

    const float NEG_INF = -__int_as_float(0x7f800000);
    float mi[2][2], li[2][2];
#pragma unroll
    for (int b2 = 0; b2 < 2; b2++) {
        mi[b2][0] = NEG_INF; mi[b2][1] = NEG_INF;
        li[b2][0] = 0.f;     li[b2][1] = 0.f;
    }
    float o[2][8][4];
#pragma unroll
    for (int b2 = 0; b2 < 2; b2++)
#pragma unroll
        for (int i = 0; i < 8; i++)
#pragma unroll
            for (int j = 0; j < 4; j++) o[b2][i][j] = 0.f;

    const uint32_t vtile_off =
        (uint32_t)(((lane & 7) + ((lane >> 3) & 1) * 8) * SPVH * 2 +
                   (lane >> 4) * 16);

    const int nt = 2 * qt + 2;
    for (int jt = 0; jt < nt; jt++) {
        const int bsel = jt & 1;
        asm volatile("cp.async.wait_group 0;" ::: "memory");
        __syncthreads();
        if (jt + 1 < nt) issue(jt + 1, bsel ^ 1);

        const float* ksm = bsel ? Kb1 : Kb0;
        const float* vmp = bsel ? vm1b : vm0b;
        const uint32_t vb = uV[bsel] + vtile_off;

        // S = Q @ K^T : one LDS.128 per (P,n) feeds 4 MMAs (2 ks x 2 blocks)
        float s[2][8][4];
#pragma unroll
        for (int b2 = 0; b2 < 2; b2++)
#pragma unroll
            for (int n = 0; n < 8; n++)
#pragma unroll
                for (int j = 0; j < 4; j++) s[b2][n][j] = 0.f;
#pragma unroll
        for (int P = 0; P < 4; P++) {
#pragma unroll
            for (int n = 0; n < 8; n++) {
                float4 kv = *(const float4*)&ksm[(n * 8 + g) * SPK + 16 * P + 4 * t];
                uint32_t k0x = __float_as_uint(kv.x), k0y = __float_as_uint(kv.y);
                uint32_t k1x = __float_as_uint(kv.z), k1y = __float_as_uint(kv.w);
#pragma unroll
                for (int b2 = 0; b2 < 2; b2++) {
                    mma_tf32r(s[b2][n], qlo[b2][P].x, qhi[b2][P].x,
                              qlo[b2][P].y, qhi[b2][P].y, k0x, k0y);
                    mma_tf32r(s[b2][n], qlo[b2][P].z, qhi[b2][P].z,
                              qlo[b2][P].w, qhi[b2][P].w, k1x, k1y);
                }
            }
        }

        // mask + scale (base-2 domain), both blocks
#pragma unroll
        for (int n = 0; n < 8; n++) {
            float vmv0 = vmp[n * 8 + 2 * t];
            float vmv1 = vmp[n * 8 + 2 * t + 1];
            int c0 = jt * 64 + n * 8 + 2 * t;
#pragma unroll
            for (int b2 = 0; b2 < 2; b2++) {
                const int rb = qt * 128 + wr + 16 * b2 + g;
                float s0 = s[b2][n][0] * SCALE2 - (1.f - vmv0) * BIG2;
                float s1 = s[b2][n][1] * SCALE2 - (1.f - vmv1) * BIG2;
                float s2 = s[b2][n][2] * SCALE2 - (1.f - vmv0) * BIG2;
                float s3 = s[b2][n][3] * SCALE2 - (1.f - vmv1) * BIG2;
                if (c0 > rb) s0 -= BIG2;
                if (c0 + 1 > rb) s1 -= BIG2;
                if (c0 > rb + 8) s2 -= BIG2;
                if (c0 + 1 > rb + 8) s3 -= BIG2;
                s[b2][n][0] = s0; s[b2][n][1] = s1;
                s[b2][n][2] = s2; s[b2][n][3] = s3;
            }
        }

        // online softmax per block
#pragma unroll
        for (int b2 = 0; b2 < 2; b2++) {
            float rm0 = NEG_INF, rm1 = NEG_INF;
#pragma unroll
            for (int n = 0; n < 8; n++) {
                rm0 = fmaxf(rm0, fmaxf(s[b2][n][0], s[b2][n][1]));
                rm1 = fmaxf(rm1, fmaxf(s[b2][n][2], s[b2][n][3]));
            }
            rm0 = fmaxf(rm0, __shfl_xor_sync(0xffffffffu, rm0, 1));
            rm0 = fmaxf(rm0, __shfl_xor_sync(0xffffffffu, rm0, 2));
            rm1 = fmaxf(rm1, __shfl_xor_sync(0xffffffffu, rm1, 1));
            rm1 = fmaxf(rm1, __shfl_xor_sync(0xffffffffu, rm1, 2));

            float mn0 = fmaxf(mi[b2][0], rm0), mn1 = fmaxf(mi[b2][1], rm1);
            float cr0 = ex2f(mi[b2][0] - mn0), cr1 = ex2f(mi[b2][1] - mn1);
            float rs0 = 0.f, rs1 = 0.f;
#pragma unroll
            for (int n = 0; n < 8; n++) {
                s[b2][n][0] = ex2f(s[b2][n][0] - mn0);
                s[b2][n][1] = ex2f(s[b2][n][1] - mn0);
                s[b2][n][2] = ex2f(s[b2][n][2] - mn1);
                s[b2][n][3] = ex2f(s[b2][n][3] - mn1);
                rs0 += s[b2][n][0] + s[b2][n][1];
                rs1 += s[b2][n][2] + s[b2][n][3];
            }
            rs0 += __shfl_xor_sync(0xffffffffu, rs0, 1);
            rs0 += __shfl_xor_sync(0xffffffffu, rs0, 2);
            rs1 += __shfl_xor_sync(0xffffffffu, rs1, 1);
            rs1 += __shfl_xor_sync(0xffffffffu, rs1, 2);
            li[b2][0] = li[b2][0] * cr0 + rs0;
            li[b2][1] = li[b2][1] * cr1 + rs1;
            mi[b2][0] = mn0; mi[b2][1] = mn1;
#pragma unroll
            for (int nd = 0; nd < 8; nd++) {
                o[b2][nd][0] *= cr0; o[b2][nd][1] *= cr0;
                o[b2][nd][2] *= cr1; o[b2][nd][3] *= cr1;
            }
        }

        // O += P @ V : each ldmatrix B-frag feeds both blocks' MMAs
#pragma unroll
        for (int kb = 0; kb < 4; kb++) {
            uint32_t a0 = packh2(s[0][2 * kb][0], s[0][2 * kb][1]);
            uint32_t a1 = packh2(s[0][2 * kb][2], s[0][2 * kb][3]);
            uint32_t a2 = packh2(s[0][2 * kb + 1][0], s[0][2 * kb + 1][1]);
            uint32_t a3 = packh2(s[0][2 * kb + 1][2], s[0][2 * kb + 1][3]);
            uint32_t c0 = packh2(s[1][2 * kb][0], s[1][2 * kb][1]);
            uint32_t c1 = packh2(s[1][2 * kb][2], s[1][2 * kb][3]);
            uint32_t c2 = packh2(s[1][2 * kb + 1][0], s[1][2 * kb + 1][1]);
            uint32_t c3 = packh2(s[1][2 * kb + 1][2], s[1][2 * kb + 1][3]);
            uint32_t rowoff = (uint32_t)(kb * 16 * SPVH * 2);
#pragma unroll
            for (int dp = 0; dp < 4; dp++) {
                uint32_t b0, b1, b2v, b3;
                asm volatile(
                    "ldmatrix.sync.aligned.m8n8.x4.trans.shared.b16 "
                    "{%0,%1,%2,%3}, [%4];"
                    : "=r"(b0), "=r"(b1), "=r"(b2v), "=r"(b3)
                    : "r"(vb + rowoff + dp * 32));
                mma_f16(o[0][2 * dp], a0, a1, a2, a3, b0, b1);
                mma_f16(o[0][2 * dp + 1], a0, a1, a2, a3, b2v, b3);
                mma_f16(o[1][2 * dp], c0, c1, c2, c3, b0, b1);
                mma_f16(o[1][2 * dp + 1], c0, c1, c2, c3, b2v, b3);
            }
        }
    }

    // Epilogue
#pragma unroll
    for (int b2 = 0; b2 < 2; b2++) {
        int r0 = qt * 128 + wr + 16 * b2 + g;
        int r1 = r0 + 8;
        float sc0 = qmask[(size_t)b_ * Ss + r0] / li[b2][0];
        float sc1 = qmask[(size_t)b_ * Ss + r1] / li[b2][1];
        float* ob0 = out + ((size_t)b_ * Ss + r0) * DM + h * 64;
        float* ob1 = out + ((size_t)b_ * Ss + r1) * DM + h * 64;
#pragma unroll
        for (int nd = 0; nd < 8; nd++) {
            *(float2*)&ob0[nd * 8 + 2 * t] =
                make_float2(o[b2][nd][0] * sc0, o[b2][nd][1] * sc0);
            *(float2*)&ob1[nd * 8 + 2 * t] =
                make_float2(o[b2][nd][2] * sc1, o[b2][nd][3] * sc1);
        }
    }
}

extern "C" void kernel_launch(void* const* d_in, const int* in_sizes, int n_in,
                              void* d_out, int out_size)
{
    const float* q     = (const float*)d_in[0];
    const float* k     = (const float*)d_in[1];
    const float* v     = (const float*)d_in[2];
    const float* vmask = (const float*)d_in[3];
    const float* qmask = (const float*)d_in[4];
    const float* Wq    = (const float*)d_in[5];
    const float* Wk    = (const float*)d_in[6];
    const float* Wv    = (const float*)d_in[7];
    float* out = (float*)d_out;

    int proj_smem = PROJ_SMEM_FLOATS * sizeof(float);
    cudaFuncSetAttribute(proj_mma_kernel,
                         cudaFuncAttributeMaxDynamicSharedMemorySize, proj_smem);
    dim3 pg(DM / 128, (Bb * Ss) / 128, 3);
    proj_mma_kernel<<<pg, 256, proj_smem>>>(q, k, v, Wq, Wk, Wv);

    int fa_smem = FA_SMEM_FLOATS * sizeof(float);
    cudaFuncSetAttribute(fa_mma_kernel,
                         cudaFuncAttributeMaxDynamicSharedMemorySize, fa_smem);
    dim3 fg(Ss / 128, Bb * Hh);
    fa_mma_kernel<<<fg, 128, fa_smem>>>(vmask, qmask, out);
}

// round 11
// speedup vs baseline: 4.5405x; 1.0448x over previous
#include <cuda_runtime.h>
#include <cuda_fp16.h>
#include <cstdint>

#define Bb 4
#define Ss 2048
#define DM 1024
#define Hh 16
#define Dh 64
// base-2 domain constants
#define SCALE2 0.18033688011112042f   /* 0.125 * log2(e) */
#define BIG2   1.4426950408889634e10f /* 1e10 * log2(e) */

// Scratch (allocation-free rule: __device__ globals). All projections fp16.
__device__ __half g_qh[Bb * Hh * Ss * Dh];
__device__ __half g_kh[Bb * Hh * Ss * Dh];
__device__ __half g_vh[Bb * Hh * Ss * Dh];

__device__ __forceinline__ uint32_t smem_u32(const void* p) {
    uint32_t a;
    asm("{ .reg .u64 t; cvta.to.shared.u64 t, %1; cvt.u32.u64 %0, t; }"
        : "=r"(a) : "l"(p));
    return a;
}
__device__ __forceinline__ float ex2f(float x) {
    float r;
    asm("ex2.approx.ftz.f32 %0, %1;" : "=f"(r) : "f"(x));
    return r;
}
__device__ __forceinline__ uint32_t packh2(float lo, float hi) {
    uint32_t r;  // d<15:0> = cvt(lo), d<31:16> = cvt(hi)
    asm("cvt.rn.f16x2.f32 %0, %1, %2;" : "=r"(r) : "f"(hi), "f"(lo));
    return r;
}
__device__ __forceinline__ void cp_async16(uint32_t dst, const void* src) {
    asm volatile("cp.async.cg.shared.global [%0], [%1], 16;"
                 :: "r"(dst), "l"(src) : "memory");
}
__device__ __forceinline__ void mma_f16(float* d, uint32_t a0, uint32_t a1,
                                        uint32_t a2, uint32_t a3,
                                        uint32_t b0, uint32_t b1) {
    asm volatile(
        "mma.sync.aligned.m16n8k16.row.col.f32.f16.f16.f32 "
        "{%0,%1,%2,%3}, {%4,%5,%6,%7}, {%8,%9}, {%0,%1,%2,%3};"
        : "+f"(d[0]), "+f"(d[1]), "+f"(d[2]), "+f"(d[3])
        : "r"(a0), "r"(a1), "r"(a2), "r"(a3), "r"(b0), "r"(b1));
}

// ---------------------------------------------------------------------------
// Projection GEMM: fp32 X [M,K], W [K,N] from d_in; fragments packed to fp16
// at LDS time; m16n8k16.f16 MMA, fp32 accum. CTA 128x128, BK=32, 3-stage.
// Epilogue: stage fp32 C in smem, coalesced fp16 sweep to g_{q,k,v}h.
// ---------------------------------------------------------------------------
#define BK2 32
#define PA 36
#define PB 136
#define PC 132
#define A_ST (128 * PA)
#define B_ST (BK2 * PB)
#define PROJ_SMEM_FLOATS (3 * (A_ST + B_ST))

__global__ __launch_bounds__(256, 2)
void proj_mma_kernel(const float* __restrict__ qin,
                     const float* __restrict__ kin,
                     const float* __restrict__ vin,
                     const float* __restrict__ Wq,
                     const float* __restrict__ Wk,
                     const float* __restrict__ Wv)
{
    extern __shared__ float psm[];
    const int z = blockIdx.z;
    const float* X = (z == 0) ? qin : (z == 1) ? kin : vin;
    const float* W = (z == 0) ? Wq : (z == 1) ? Wk : Wv;
    __half* O = (z == 0) ? g_qh : (z == 1) ? g_kh : g_vh;

    const int m0 = blockIdx.y * 128;
    const int n0 = blockIdx.x * 128;
    const int tid = threadIdx.x;
    const int lane = tid & 31;
    const int warp = tid >> 5;
    const int wm = (warp >> 2) * 64;
    const int wn = (warp & 3) * 32;
    const int g = lane >> 2, t = lane & 3;

    uint32_t uA[3], uB[3];
#pragma unroll
    for (int i = 0; i < 3; i++) {
        uA[i] = smem_u32(psm + i * (A_ST + B_ST));
        uB[i] = smem_u32(psm + i * (A_ST + B_ST) + A_ST);
    }

    float acc[4][4][4];
#pragma unroll
    for (int i = 0; i < 4; i++)
#pragma unroll
        for (int j = 0; j < 4; j++)
#pragma unroll
            for (int c = 0; c < 4; c++) acc[i][j][c] = 0.f;

    auto issue = [&](int kt) {
        const int st = kt % 3;
        const int k0 = kt * BK2;
#pragma unroll
        for (int i = 0; i < 4; i++) {
            int idx = tid + i * 256;
            int row = idx >> 3, c4 = (idx & 7) * 4;
            cp_async16(uA[st] + (uint32_t)(row * PA + c4) * 4,
                       &X[(size_t)(m0 + row) * DM + k0 + c4]);
        }
#pragma unroll
        for (int i = 0; i < 4; i++) {
            int idx = tid + i * 256;
            int row = idx >> 5, c4 = (idx & 31) * 4;
            cp_async16(uB[st] + (uint32_t)(row * PB + c4) * 4,
                       &W[(size_t)(k0 + row) * DM + n0 + c4]);
        }
        asm volatile("cp.async.commit_group;" ::: "memory");
    };

    issue(0);
    issue(1);

    const int NSTAGE = DM / BK2;   // 32
    for (int kt = 0; kt < NSTAGE; kt++) {
        if (kt + 2 < NSTAGE)
            asm volatile("cp.async.wait_group 1;" ::: "memory");
        else
            asm volatile("cp.async.wait_group 0;" ::: "memory");
        __syncthreads();
        if (kt + 2 < NSTAGE) issue(kt + 2);

        const int st = kt % 3;
        const float* as = psm + st * (A_ST + B_ST);
        const float* bs = as + A_ST;
#pragma unroll
        for (int kc = 0; kc < 2; kc++) {
            uint32_t a[4][4];
#pragma unroll
            for (int mf = 0; mf < 4; mf++) {
                const float* p = &as[(wm + mf * 16 + g) * PA + kc * 16 + 2 * t];
                float2 v00 = *(const float2*)p;            // row g,   k 2t..
                float2 v01 = *(const float2*)(p + 8);      // row g,   k 2t+8..
                float2 v10 = *(const float2*)(p + 8 * PA); // row g+8, k 2t..
                float2 v11 = *(const float2*)(p + 8 * PA + 8);
                a[mf][0] = packh2(v00.x, v00.y);
                a[mf][1] = packh2(v10.x, v10.y);
                a[mf][2] = packh2(v01.x, v01.y);
                a[mf][3] = packh2(v11.x, v11.y);
            }
            uint32_t bb[4][2];
#pragma unroll
            for (int nf = 0; nf < 4; nf++) {
                const float* pb = &bs[(kc * 16 + 2 * t) * PB + wn + nf * 8 + g];
                bb[nf][0] = packh2(pb[0], pb[PB]);
                const float* pb2 = pb + 8 * PB;
                bb[nf][1] = packh2(pb2[0], pb2[PB]);
            }
#pragma unroll
            for (int mf = 0; mf < 4; mf++)
#pragma unroll
                for (int nf = 0; nf < 4; nf++)
                    mma_f16(acc[mf][nf], a[mf][0], a[mf][1], a[mf][2], a[mf][3],
                            bb[nf][0], bb[nf][1]);
        }
    }

    // ---- Epilogue: stage fp32 tile into smem, coalesced fp16 sweep ----
    __syncthreads();
    float* ct = psm;   // [128][PC=132]
    const int j0 = 2 * t;

#pragma unroll
    for (int mf = 0; mf < 4; mf++) {
#pragma unroll
        for (int nf = 0; nf < 4; nf++) {
            int ml = wm + mf * 16 + g;
            int nb = wn + nf * 8;
            ct[ml * PC + nb + j0]           = acc[mf][nf][0];
            ct[ml * PC + nb + j0 + 1]       = acc[mf][nf][1];
            ct[(ml + 8) * PC + nb + j0]     = acc[mf][nf][2];
            ct[(ml + 8) * PC + nb + j0 + 1] = acc[mf][nf][3];
        }
    }
    __syncthreads();

#pragma unroll
    for (int i = 0; i < 16; i++) {
        int idx = tid + i * 256;
        int row = idx >> 5;
        int c4 = (idx & 31) * 4;
        float4 val = *(const float4*)&ct[row * PC + c4];
        int m = m0 + row;
        int n = n0 + c4;
        int b_ = m >> 11, s = m & 2047, h = n >> 6, d = n & 63;
        size_t base = ((((size_t)b_ * Hh + h) * Ss) + s) * Dh + d;
        __half2 h01 = __floats2half2_rn(val.x, val.y);
        __half2 h23 = __floats2half2_rn(val.z, val.w);
        uint2 pk = make_uint2(*(uint32_t*)&h01, *(uint32_t*)&h23);
        *(uint2*)&O[base] = pk;
    }
}

// ---------------------------------------------------------------------------
// Flash attention: all-fp16 MMA (QK^T and PV both m16n8k16, fp32 accum).
// 128 threads (4 warps x 32 q-rows), Q frags register-cached from gmem,
// K frags via conflict-free LDS.32 (stride 72 halves -> banks 4g+t),
// V via ldmatrix.trans. Double-buffered cp.async, 2 CTAs/SM.
// ---------------------------------------------------------------------------
#define SPKH 72     /* K smem stride in halves */
#define SPVH 72     /* V smem stride in halves */
#define KV_FL 2304  /* 64*72 halves = 2304 floats per buffer */
#define FA_SMEM_FLOATS (4 * KV_FL + 128)   /* 9344 fl = 37.4 KB */

__global__ __launch_bounds__(128, 2)
void fa_mma_kernel(const float* __restrict__ vmask,
                   const float* __restrict__ qmask, float* __restrict__ out)
{
    extern __shared__ float sm[];
    __half* Kh0  = (__half*)sm;
    __half* Kh1  = (__half*)(sm + KV_FL);
    __half* Vh0  = (__half*)(sm + 2 * KV_FL);
    __half* Vh1  = (__half*)(sm + 3 * KV_FL);
    float*  vm0b = sm + 4 * KV_FL;
    float*  vm1b = vm0b + 64;

    const int qt = (int)gridDim.x - 1 - (int)blockIdx.x;  // heavy tiles first
    const int bh = blockIdx.y;
    const int b_ = bh >> 4, h = bh & 15;
    const int tid = threadIdx.x, lane = tid & 31, wid = tid >> 5;
    const int g = lane >> 2, t = lane & 3;
    const int wr = wid * 32;

    const uint32_t uK[2] = { smem_u32(Kh0), smem_u32(Kh1) };
    const uint32_t uV[2] = { smem_u32(Vh0), smem_u32(Vh1) };
    const uint32_t uM[2] = { smem_u32(vm0b), smem_u32(vm1b) };

    const __half* Kg = &g_kh[(size_t)bh * Ss * Dh];
    const __half* Vg = &g_vh[(size_t)bh * Ss * Dh];

    auto issue = [&](int jt, int bsel) {
        // K: 64 rows x 128B = 512 chunks, 4 per thread
#pragma unroll
        for (int i = 0; i < 4; i++) {
            int idx = tid + i * 128;
            int row = idx >> 3, c16 = idx & 7;
            cp_async16(uK[bsel] + (uint32_t)(row * SPKH * 2 + c16 * 16),
                       Kg + (size_t)(jt * 64 + row) * Dh + c16 * 8);
        }
        // V: same shape
#pragma unroll
        for (int i = 0; i < 4; i++) {
            int idx = tid + i * 128;
            int row = idx >> 3, c16 = idx & 7;
            cp_async16(uV[bsel] + (uint32_t)(row * SPVH * 2 + c16 * 16),
                       Vg + (size_t)(jt * 64 + row) * Dh + c16 * 8);
        }
        if (tid < 16)
            cp_async16(uM[bsel] + tid * 16,
                       vmask + (size_t)b_ * Ss + jt * 64 + tid * 4);
        asm volatile("cp.async.commit_group;" ::: "memory");
    };

    issue(0, 0);

    // Q fragments register-cached (fp16, natural layout) for the whole loop.
    uint4 q[2][4];
    {
        const __half* Qg = &g_qh[((size_t)bh * Ss + qt * 128) * Dh];
#pragma unroll
        for (int b2 = 0; b2 < 2; b2++)
#pragma unroll
            for (int P = 0; P < 4; P++) {
                int r = wr + 16 * b2 + g;
                uint32_t a0 = *(const uint32_t*)&Qg[(size_t)r * Dh + 16 * P + 2 * t];
                uint32_t a1 = *(const uint32_t*)&Qg[(size_t)(r + 8) * Dh + 16 * P + 2 * t];
                uint32_t a2 = *(const uint32_t*)&Qg[(size_t)r * Dh + 16 * P + 8 + 2 * t];
                uint32_t a3 = *(const uint32_t*)&Qg[(size_t)(r + 8) * Dh + 16 * P + 8 + 2 * t];
                q[b2][P] = make_uint4(a0, a1, a2, a3);
            }
    }

    const float NEG_INF = -__int_as_float(0x7f800000);
    float mi[2][2], li[2][2];
#pragma unroll
    for (int b2 = 0; b2 < 2; b2++) {
        mi[b2][0] = NEG_INF; mi[b2][1] = NEG_INF;
        li[b2][0] = 0.f;     li[b2][1] = 0.f;
    }
    float o[2][8][4];
#pragma unroll
    for (int b2 = 0; b2 < 2; b2++)
#pragma unroll
        for (int i = 0; i < 8; i++)
#pragma unroll
            for (int j = 0; j < 4; j++) o[b2][i][j] = 0.f;

    const uint32_t vtile_off =
        (uint32_t)(((lane & 7) + ((lane >> 3) & 1) * 8) * SPVH * 2 +
                   (lane >> 4) * 16);

    const int nt = 2 * qt + 2;
    for (int jt = 0; jt < nt; jt++) {
        const int bsel = jt & 1;
        asm volatile("cp.async.wait_group 0;" ::: "memory");
        __syncthreads();
        if (jt + 1 < nt) issue(jt + 1, bsel ^ 1);

        const __half* ksm = bsel ? Kh1 : Kh0;
        const float*  vmp = bsel ? vm1b : vm0b;
        const uint32_t vb = uV[bsel] + vtile_off;

        // S = Q @ K^T : fp16 m16n8k16; each K-frag load feeds both blocks.
        float s[2][8][4];
#pragma unroll
        for (int b2 = 0; b2 < 2; b2++)
#pragma unroll
            for (int n = 0; n < 8; n++)
#pragma unroll
                for (int j = 0; j < 4; j++) s[b2][n][j] = 0.f;
#pragma unroll
        for (int P = 0; P < 4; P++) {
#pragma unroll
            for (int n = 0; n < 8; n++) {
                uint32_t b0 = *(const uint32_t*)
                    &ksm[(n * 8 + g) * SPKH + 16 * P + 2 * t];
                uint32_t b1 = *(const uint32_t*)
                    &ksm[(n * 8 + g) * SPKH + 16 * P + 8 + 2 * t];
                mma_f16(s[0][n], q[0][P].x, q[0][P].y, q[0][P].z, q[0][P].w,
                        b0, b1);
                mma_f16(s[1][n], q[1][P].x, q[1][P].y, q[1][P].z, q[1][P].w,
                        b0, b1);
            }
        }

        // mask + scale (base-2 domain)
#pragma unroll
        for (int n = 0; n < 8; n++) {
            float vmv0 = vmp[n * 8 + 2 * t];
            float vmv1 = vmp[n * 8 + 2 * t + 1];
            int c0 = jt * 64 + n * 8 + 2 * t;
#pragma unroll
            for (int b2 = 0; b2 < 2; b2++) {
                const int rb = qt * 128 + wr + 16 * b2 + g;
                float s0 = s[b2][n][0] * SCALE2 - (1.f - vmv0) * BIG2;
                float s1 = s[b2][n][1] * SCALE2 - (1.f - vmv1) * BIG2;
                float s2 = s[b2][n][2] * SCALE2 - (1.f - vmv0) * BIG2;
                float s3 = s[b2][n][3] * SCALE2 - (1.f - vmv1) * BIG2;
                if (c0 > rb) s0 -= BIG2;
                if (c0 + 1 > rb) s1 -= BIG2;
                if (c0 > rb + 8) s2 -= BIG2;
                if (c0 + 1 > rb + 8) s3 -= BIG2;
                s[b2][n][0] = s0; s[b2][n][1] = s1;
                s[b2][n][2] = s2; s[b2][n][3] = s3;
            }
        }

        // online softmax per block
#pragma unroll
        for (int b2 = 0; b2 < 2; b2++) {
            float rm0 = NEG_INF, rm1 = NEG_INF;
#pragma unroll
            for (int n = 0; n < 8; n++) {
                rm0 = fmaxf(rm0, fmaxf(s[b2][n][0], s[b2][n][1]));
                rm1 = fmaxf(rm1, fmaxf(s[b2][n][2], s[b2][n][3]));
            }
            rm0 = fmaxf(rm0, __shfl_xor_sync(0xffffffffu, rm0, 1));
            rm0 = fmaxf(rm0, __shfl_xor_sync(0xffffffffu, rm0, 2));
            rm1 = fmaxf(rm1, __shfl_xor_sync(0xffffffffu, rm1, 1));
            rm1 = fmaxf(rm1, __shfl_xor_sync(0xffffffffu, rm1, 2));

            float mn0 = fmaxf(mi[b2][0], rm0), mn1 = fmaxf(mi[b2][1], rm1);
            float cr0 = ex2f(mi[b2][0] - mn0), cr1 = ex2f(mi[b2][1] - mn1);
            float rs0 = 0.f, rs1 = 0.f;
#pragma unroll
            for (int n = 0; n < 8; n++) {
                s[b2][n][0] = ex2f(s[b2][n][0] - mn0);
                s[b2][n][1] = ex2f(s[b2][n][1] - mn0);
                s[b2][n][2] = ex2f(s[b2][n][2] - mn1);
                s[b2][n][3] = ex2f(s[b2][n][3] - mn1);
                rs0 += s[b2][n][0] + s[b2][n][1];
                rs1 += s[b2][n][2] + s[b2][n][3];
            }
            rs0 += __shfl_xor_sync(0xffffffffu, rs0, 1);
            rs0 += __shfl_xor_sync(0xffffffffu, rs0, 2);
            rs1 += __shfl_xor_sync(0xffffffffu, rs1, 1);
            rs1 += __shfl_xor_sync(0xffffffffu, rs1, 2);
            li[b2][0] = li[b2][0] * cr0 + rs0;
            li[b2][1] = li[b2][1] * cr1 + rs1;
            mi[b2][0] = mn0; mi[b2][1] = mn1;
#pragma unroll
            for (int nd = 0; nd < 8; nd++) {
                o[b2][nd][0] *= cr0; o[b2][nd][1] *= cr0;
                o[b2][nd][2] *= cr1; o[b2][nd][3] *= cr1;
            }
        }

        // O += P @ V : each ldmatrix B-frag feeds both blocks' MMAs
#pragma unroll
        for (int kb = 0; kb < 4; kb++) {
            uint32_t a0 = packh2(s[0][2 * kb][0], s[0][2 * kb][1]);
            uint32_t a1 = packh2(s[0][2 * kb][2], s[0][2 * kb][3]);
            uint32_t a2 = packh2(s[0][2 * kb + 1][0], s[0][2 * kb + 1][1]);
            uint32_t a3 = packh2(s[0][2 * kb + 1][2], s[0][2 * kb + 1][3]);
            uint32_t c0 = packh2(s[1][2 * kb][0], s[1][2 * kb][1]);
            uint32_t c1 = packh2(s[1][2 * kb][2], s[1][2 * kb][3]);
            uint32_t c2 = packh2(s[1][2 * kb + 1][0], s[1][2 * kb + 1][1]);
            uint32_t c3 = packh2(s[1][2 * kb + 1][2], s[1][2 * kb + 1][3]);
            uint32_t rowoff = (uint32_t)(kb * 16 * SPVH * 2);
#pragma unroll
            for (int dp = 0; dp < 4; dp++) {
                uint32_t b0, b1, b2v, b3;
                asm volatile(
                    "ldmatrix.sync.aligned.m8n8.x4.trans.shared.b16 "
                    "{%0,%1,%2,%3}, [%4];"
                    : "=r"(b0), "=r"(b1), "=r"(b2v), "=r"(b3)
                    : "r"(vb + rowoff + dp * 32));
                mma_f16(o[0][2 * dp], a0, a1, a2, a3, b0, b1);
                mma_f16(o[0][2 * dp + 1], a0, a1, a2, a3, b2v, b3);
                mma_f16(o[1][2 * dp], c0, c1, c2, c3, b0, b1);
                mma_f16(o[1][2 * dp + 1], c0, c1, c2, c3, b2v, b3);
            }
        }
    }

    // Epilogue
#pragma unroll
    for (int b2 = 0; b2 < 2; b2++) {
        int r0 = qt * 128 + wr + 16 * b2 + g;
        int r1 = r0 + 8;
        float sc0 = qmask[(size_t)b_ * Ss + r0] / li[b2][0];
        float sc1 = qmask[(size_t)b_ * Ss + r1] / li[b2][1];
        float* ob0 = out + ((size_t)b_ * Ss + r0) * DM + h * 64;
        float* ob1 = out + ((size_t)b_ * Ss + r1) * DM + h * 64;
#pragma unroll
        for (int nd = 0; nd < 8; nd++) {
            *(float2*)&ob0[nd * 8 + 2 * t] =
                make_float2(o[b2][nd][0] * sc0, o[b2][nd][1] * sc0);
            *(float2*)&ob1[nd * 8 + 2 * t] =
                make_float2(o[b2][nd][2] * sc1, o[b2][nd][3] * sc1);
        }
    }
}

extern "C" void kernel_launch(void* const* d_in, const int* in_sizes, int n_in,
                              void* d_out, int out_size)
{
    const float* q     = (const float*)d_in[0];
    const float* k     = (const float*)d_in[1];
    const float* v     = (const float*)d_in[2];
    const float* vmask = (const float*)d_in[3];
    const float* qmask = (const float*)d_in[4];
    const float* Wq    = (const float*)d_in[5];
    const float* Wk    = (const float*)d_in[6];
    const float* Wv    = (const float*)d_in[7];
    float* out = (float*)d_out;

    int proj_smem = PROJ_SMEM_FLOATS * sizeof(float);
    cudaFuncSetAttribute(proj_mma_kernel,
                         cudaFuncAttributeMaxDynamicSharedMemorySize, proj_smem);
    dim3 pg(DM / 128, (Bb * Ss) / 128, 3);
    proj_mma_kernel<<<pg, 256, proj_smem>>>(q, k, v, Wq, Wk, Wv);

    int fa_smem = FA_SMEM_FLOATS * sizeof(float);
    cudaFuncSetAttribute(fa_mma_kernel,
                         cudaFuncAttributeMaxDynamicSharedMemorySize, fa_smem);
    dim3 fg(Ss / 128, Bb * Hh);
    fa_mma_kernel<<<fg, 128, fa_smem>>>(vmask, qmask, out);
}

// round 12
// speedup vs baseline: 7.3017x; 1.6081x over previous
#include <cuda_runtime.h>
#include <cuda_fp16.h>
#include <cstdint>

#define Bb 4
#define Ss 2048
#define DM 1024
#define Hh 16
#define Dh 64
// base-2 domain constants
#define SCALE2 0.18033688011112042f   /* 0.125 * log2(e) */
#define BIG2   1.4426950408889634e10f /* 1e10 * log2(e) */

#define XN 8388608ULL   /* Bb*Ss*DM */
#define WN 1048576ULL   /* DM*DM */

// Scratch (allocation-free rule: __device__ globals).
__device__ __half g_qh[Bb * Hh * Ss * Dh];
__device__ __half g_kh[Bb * Hh * Ss * Dh];
__device__ __half g_vh[Bb * Hh * Ss * Dh];
__device__ __half g_xh[3 * XN];   // fp16 copies of q,k,v inputs
__device__ __half g_wh[3 * WN];   // fp16 copies of Wq,Wk,Wv

__device__ __forceinline__ uint32_t smem_u32(const void* p) {
    uint32_t a;
    asm("{ .reg .u64 t; cvta.to.shared.u64 t, %1; cvt.u32.u64 %0, t; }"
        : "=r"(a) : "l"(p));
    return a;
}
__device__ __forceinline__ float ex2f(float x) {
    float r;
    asm("ex2.approx.ftz.f32 %0, %1;" : "=f"(r) : "f"(x));
    return r;
}
__device__ __forceinline__ uint32_t packh2(float lo, float hi) {
    uint32_t r;  // d<15:0> = cvt(lo), d<31:16> = cvt(hi)
    asm("cvt.rn.f16x2.f32 %0, %1, %2;" : "=r"(r) : "f"(hi), "f"(lo));
    return r;
}
__device__ __forceinline__ void cp_async16(uint32_t dst, const void* src) {
    asm volatile("cp.async.cg.shared.global [%0], [%1], 16;"
                 :: "r"(dst), "l"(src) : "memory");
}
__device__ __forceinline__ void mma_f16(float* d, uint32_t a0, uint32_t a1,
                                        uint32_t a2, uint32_t a3,
                                        uint32_t b0, uint32_t b1) {
    asm volatile(
        "mma.sync.aligned.m16n8k16.row.col.f32.f16.f16.f32 "
        "{%0,%1,%2,%3}, {%4,%5,%6,%7}, {%8,%9}, {%0,%1,%2,%3};"
        : "+f"(d[0]), "+f"(d[1]), "+f"(d[2]), "+f"(d[3])
        : "r"(a0), "r"(a1), "r"(a2), "r"(a3), "r"(b0), "r"(b1));
}

// ---------------------------------------------------------------------------
// Pre-pass: convert X (q,k,v) and W (Wq,Wk,Wv) fp32 -> fp16 gmem copies.
// grid (9216, 3): bx<8192 -> X chunk, else W chunk.
// ---------------------------------------------------------------------------
__global__ __launch_bounds__(256)
void cvt16_kernel(const float* __restrict__ q, const float* __restrict__ k,
                  const float* __restrict__ v, const float* __restrict__ Wq,
                  const float* __restrict__ Wk, const float* __restrict__ Wv)
{
    const int z = blockIdx.y;
    const float* src;
    __half* dst;
    size_t i;
    if (blockIdx.x < 8192) {
        src = (z == 0) ? q : (z == 1) ? k : v;
        dst = g_xh + z * XN;
        i = ((size_t)blockIdx.x * 256 + threadIdx.x) * 4;
    } else {
        src = (z == 0) ? Wq : (z == 1) ? Wk : Wv;
        dst = g_wh + z * WN;
        i = ((size_t)(blockIdx.x - 8192) * 256 + threadIdx.x) * 4;
    }
    float4 x = *(const float4*)&src[i];
    __half2 h01 = __floats2half2_rn(x.x, x.y);
    __half2 h23 = __floats2half2_rn(x.z, x.w);
    *(uint2*)&dst[i] = make_uint2(*(uint32_t*)&h01, *(uint32_t*)&h23);
}

// ---------------------------------------------------------------------------
// Projection GEMM, all-fp16 smem + ldmatrix fragments.
// CTA 128x128, BK=64, double-buffered cp.async. 8 warps (2x4), warp 64x32.
// A [M,K] fp16 stride 72 halves; B [K,N] fp16 stride 136 halves.
// Epilogue: fp16 staging tile, coalesced uint4 sweep into [B,H,S,64].
// ---------------------------------------------------------------------------
#define PAH 72                    /* A smem stride (halves), 144B: 8-row conflict-free */
#define PBH 136                   /* B smem stride (halves), 272B: 8-row conflict-free */
#define AH_ST (128 * PAH)         /* 9216 halves */
#define BH_ST (64 * PBH)          /* 8704 halves */
#define STG_H (AH_ST + BH_ST)     /* 17920 halves per stage */
#define PROJ_SMEM_BYTES (2 * STG_H * 2)   /* 71680 B */
#define PCH 136                   /* epilogue staging stride (halves) */

__global__ __launch_bounds__(256, 2)
void proj_h_kernel()
{
    extern __shared__ __half hsm[];
    const int z = blockIdx.z;
    const __half* X = g_xh + z * XN;
    const __half* W = g_wh + z * WN;
    __half* O = (z == 0) ? g_qh : (z == 1) ? g_kh : g_vh;

    const int m0 = blockIdx.y * 128;
    const int n0 = blockIdx.x * 128;
    const int tid = threadIdx.x;
    const int lane = tid & 31;
    const int warp = tid >> 5;
    const int wm = (warp >> 2) * 64;
    const int wn = (warp & 3) * 32;
    const int g = lane >> 2, t = lane & 3;

    uint32_t uA[2], uB[2];
#pragma unroll
    for (int i = 0; i < 2; i++) {
        uA[i] = smem_u32(hsm + i * STG_H);
        uB[i] = uA[i] + AH_ST * 2;
    }

    float acc[4][4][4];
#pragma unroll
    for (int i = 0; i < 4; i++)
#pragma unroll
        for (int j = 0; j < 4; j++)
#pragma unroll
            for (int c = 0; c < 4; c++) acc[i][j][c] = 0.f;

    auto issue = [&](int kt) {
        const int st = kt & 1;
        const int k0 = kt * 64;
        // A: 128 rows x 128B -> 1024 chunks, 4/thread
#pragma unroll
        for (int i = 0; i < 4; i++) {
            int idx = tid + i * 256;
            int row = idx >> 3, c16 = idx & 7;
            cp_async16(uA[st] + (uint32_t)(row * PAH * 2 + c16 * 16),
                       &X[(size_t)(m0 + row) * DM + k0 + c16 * 8]);
        }
        // B: 64 rows x 256B -> 1024 chunks, 4/thread
#pragma unroll
        for (int i = 0; i < 4; i++) {
            int idx = tid + i * 256;
            int row = idx >> 4, c16 = idx & 15;
            cp_async16(uB[st] + (uint32_t)(row * PBH * 2 + c16 * 16),
                       &W[(size_t)(k0 + row) * DM + n0 + c16 * 8]);
        }
        asm volatile("cp.async.commit_group;" ::: "memory");
    };

    issue(0);

    // ldmatrix per-lane offsets
    const uint32_t a_lane_off =
        (uint32_t)((lane & 15) * PAH * 2 + (lane >> 4) * 16);
    const uint32_t b_lane_off =
        (uint32_t)(((lane & 7) + ((lane >> 3) & 1) * 8) * PBH * 2 +
                   (lane >> 4) * 16);

    const int NSTAGE = DM / 64;   // 16
    for (int kt = 0; kt < NSTAGE; kt++) {
        asm volatile("cp.async.wait_group 0;" ::: "memory");
        __syncthreads();
        if (kt + 1 < NSTAGE) issue(kt + 1);

        const int st = kt & 1;
        const uint32_t uAs = uA[st];
        const uint32_t uBs = uB[st];
#pragma unroll
        for (int kc = 0; kc < 4; kc++) {
            uint32_t a[4][4];
#pragma unroll
            for (int mf = 0; mf < 4; mf++) {
                uint32_t addr = uAs +
                    (uint32_t)((wm + mf * 16) * PAH + kc * 16) * 2 + a_lane_off;
                asm volatile(
                    "ldmatrix.sync.aligned.m8n8.x4.shared.b16 "
                    "{%0,%1,%2,%3}, [%4];"
                    : "=r"(a[mf][0]), "=r"(a[mf][1]),
                      "=r"(a[mf][2]), "=r"(a[mf][3])
                    : "r"(addr));
            }
            uint32_t brow = uBs + (uint32_t)(kc * 16 * PBH) * 2 + b_lane_off;
#pragma unroll
            for (int dp = 0; dp < 2; dp++) {
                uint32_t b0, b1, b2, b3;
                asm volatile(
                    "ldmatrix.sync.aligned.m8n8.x4.trans.shared.b16 "
                    "{%0,%1,%2,%3}, [%4];"
                    : "=r"(b0), "=r"(b1), "=r"(b2), "=r"(b3)
                    : "r"(brow + (uint32_t)(wn + dp * 16) * 2));
#pragma unroll
                for (int mf = 0; mf < 4; mf++) {
                    mma_f16(acc[mf][dp * 2], a[mf][0], a[mf][1], a[mf][2],
                            a[mf][3], b0, b1);
                    mma_f16(acc[mf][dp * 2 + 1], a[mf][0], a[mf][1], a[mf][2],
                            a[mf][3], b2, b3);
                }
            }
        }
    }

    // ---- Epilogue: fp16 staging tile, coalesced sweep ----
    __syncthreads();
    __half* ct = hsm;   // [128][PCH]
#pragma unroll
    for (int mf = 0; mf < 4; mf++) {
#pragma unroll
        for (int nf = 0; nf < 4; nf++) {
            int ml = wm + mf * 16 + g;
            int nb = wn + nf * 8 + 2 * t;
            __half2 lo = __floats2half2_rn(acc[mf][nf][0], acc[mf][nf][1]);
            __half2 hi = __floats2half2_rn(acc[mf][nf][2], acc[mf][nf][3]);
            *(__half2*)&ct[ml * PCH + nb] = lo;
            *(__half2*)&ct[(ml + 8) * PCH + nb] = hi;
        }
    }
    __syncthreads();

    // 128 rows x 256B = 2048 16B-chunks, 8/thread
#pragma unroll
    for (int i = 0; i < 8; i++) {
        int idx = tid + i * 256;
        int row = idx >> 4;
        int c16 = idx & 15;
        uint4 val = *(const uint4*)&ct[row * PCH + c16 * 8];
        int m = m0 + row;
        int n = n0 + c16 * 8;
        int b_ = m >> 11, s = m & 2047, h = n >> 6, d = n & 63;
        size_t base = ((((size_t)b_ * Hh + h) * Ss) + s) * Dh + d;
        *(uint4*)&O[base] = val;
    }
}

// ---------------------------------------------------------------------------
// Flash attention (unchanged from R11): all-fp16 MMA, 4 warps x 32 q-rows.
// ---------------------------------------------------------------------------
#define SPKH 72
#define SPVH 72
#define KV_FL 2304
#define FA_SMEM_FLOATS (4 * KV_FL + 128)

__global__ __launch_bounds__(128, 2)
void fa_mma_kernel(const float* __restrict__ vmask,
                   const float* __restrict__ qmask, float* __restrict__ out)
{
    extern __shared__ float sm[];
    __half* Kh0  = (__half*)sm;
    __half* Kh1  = (__half*)(sm + KV_FL);
    __half* Vh0  = (__half*)(sm + 2 * KV_FL);
    __half* Vh1  = (__half*)(sm + 3 * KV_FL);
    float*  vm0b = sm + 4 * KV_FL;
    float*  vm1b = vm0b + 64;

    const int qt = (int)gridDim.x - 1 - (int)blockIdx.x;
    const int bh = blockIdx.y;
    const int b_ = bh >> 4, h = bh & 15;
    const int tid = threadIdx.x, lane = tid & 31, wid = tid >> 5;
    const int g = lane >> 2, t = lane & 3;
    const int wr = wid * 32;

    const uint32_t uK[2] = { smem_u32(Kh0), smem_u32(Kh1) };
    const uint32_t uV[2] = { smem_u32(Vh0), smem_u32(Vh1) };
    const uint32_t uM[2] = { smem_u32(vm0b), smem_u32(vm1b) };

    const __half* Kg = &g_kh[(size_t)bh * Ss * Dh];
    const __half* Vg = &g_vh[(size_t)bh * Ss * Dh];

    auto issue = [&](int jt, int bsel) {
#pragma unroll
        for (int i = 0; i < 4; i++) {
            int idx = tid + i * 128;
            int row = idx >> 3, c16 = idx & 7;
            cp_async16(uK[bsel] + (uint32_t)(row * SPKH * 2 + c16 * 16),
                       Kg + (size_t)(jt * 64 + row) * Dh + c16 * 8);
        }
#pragma unroll
        for (int i = 0; i < 4; i++) {
            int idx = tid + i * 128;
            int row = idx >> 3, c16 = idx & 7;
            cp_async16(uV[bsel] + (uint32_t)(row * SPVH * 2 + c16 * 16),
                       Vg + (size_t)(jt * 64 + row) * Dh + c16 * 8);
        }
        if (tid < 16)
            cp_async16(uM[bsel] + tid * 16,
                       vmask + (size_t)b_ * Ss + jt * 64 + tid * 4);
        asm volatile("cp.async.commit_group;" ::: "memory");
    };

    issue(0, 0);

    uint4 q[2][4];
    {
        const __half* Qg = &g_qh[((size_t)bh * Ss + qt * 128) * Dh];
#pragma unroll
        for (int b2 = 0; b2 < 2; b2++)
#pragma unroll
            for (int P = 0; P < 4; P++) {
                int r = wr + 16 * b2 + g;
                uint32_t a0 = *(const uint32_t*)&Qg[(size_t)r * Dh + 16 * P + 2 * t];
                uint32_t a1 = *(const uint32_t*)&Qg[(size_t)(r + 8) * Dh + 16 * P + 2 * t];
                uint32_t a2 = *(const uint32_t*)&Qg[(size_t)r * Dh + 16 * P + 8 + 2 * t];
                uint32_t a3 = *(const uint32_t*)&Qg[(size_t)(r + 8) * Dh + 16 * P + 8 + 2 * t];
                q[b2][P] = make_uint4(a0, a1, a2, a3);
            }
    }

    const float NEG_INF = -__int_as_float(0x7f800000);
    float mi[2][2], li[2][2];
#pragma unroll
    for (int b2 = 0; b2 < 2; b2++) {
        mi[b2][0] = NEG_INF; mi[b2][1] = NEG_INF;
        li[b2][0] = 0.f;     li[b2][1] = 0.f;
    }
    float o[2][8][4];
#pragma unroll
    for (int b2 = 0; b2 < 2; b2++)
#pragma unroll
        for (int i = 0; i < 8; i++)
#pragma unroll
            for (int j = 0; j < 4; j++) o[b2][i][j] = 0.f;

    const uint32_t vtile_off =
        (uint32_t)(((lane & 7) + ((lane >> 3) & 1) * 8) * SPVH * 2 +
                   (lane >> 4) * 16);

    const int nt = 2 * qt + 2;
    for (int jt = 0; jt < nt; jt++) {
        const int bsel = jt & 1;
        asm volatile("cp.async.wait_group 0;" ::: "memory");
        __syncthreads();
        if (jt + 1 < nt) issue(jt + 1, bsel ^ 1);

        const __half* ksm = bsel ? Kh1 : Kh0;
        const float*  vmp = bsel ? vm1b : vm0b;
        const uint32_t vb = uV[bsel] + vtile_off;

        float s[2][8][4];
#pragma unroll
        for (int b2 = 0; b2 < 2; b2++)
#pragma unroll
            for (int n = 0; n < 8; n++)
#pragma unroll
                for (int j = 0; j < 4; j++) s[b2][n][j] = 0.f;
#pragma unroll
        for (int P = 0; P < 4; P++) {
#pragma unroll
            for (int n = 0; n < 8; n++) {
                uint32_t b0 = *(const uint32_t*)
                    &ksm[(n * 8 + g) * SPKH + 16 * P + 2 * t];
                uint32_t b1 = *(const uint32_t*)
                    &ksm[(n * 8 + g) * SPKH + 16 * P + 8 + 2 * t];
                mma_f16(s[0][n], q[0][P].x, q[0][P].y, q[0][P].z, q[0][P].w,
                        b0, b1);
                mma_f16(s[1][n], q[1][P].x, q[1][P].y, q[1][P].z, q[1][P].w,
                        b0, b1);
            }
        }

#pragma unroll
        for (int n = 0; n < 8; n++) {
            float vmv0 = vmp[n * 8 + 2 * t];
            float vmv1 = vmp[n * 8 + 2 * t + 1];
            int c0 = jt * 64 + n * 8 + 2 * t;
#pragma unroll
            for (int b2 = 0; b2 < 2; b2++) {
                const int rb = qt * 128 + wr + 16 * b2 + g;
                float s0 = s[b2][n][0] * SCALE2 - (1.f - vmv0) * BIG2;
                float s1 = s[b2][n][1] * SCALE2 - (1.f - vmv1) * BIG2;
                float s2 = s[b2][n][2] * SCALE2 - (1.f - vmv0) * BIG2;
                float s3 = s[b2][n][3] * SCALE2 - (1.f - vmv1) * BIG2;
                if (c0 > rb) s0 -= BIG2;
                if (c0 + 1 > rb) s1 -= BIG2;
                if (c0 > rb + 8) s2 -= BIG2;
                if (c0 + 1 > rb + 8) s3 -= BIG2;
                s[b2][n][0] = s0; s[b2][n][1] = s1;
                s[b2][n][2] = s2; s[b2][n][3] = s3;
            }
        }

#pragma unroll
        for (int b2 = 0; b2 < 2; b2++) {
            float rm0 = NEG_INF, rm1 = NEG_INF;
#pragma unroll
            for (int n = 0; n < 8; n++) {
                rm0 = fmaxf(rm0, fmaxf(s[b2][n][0], s[b2][n][1]));
                rm1 = fmaxf(rm1, fmaxf(s[b2][n][2], s[b2][n][3]));
            }
            rm0 = fmaxf(rm0, __shfl_xor_sync(0xffffffffu, rm0, 1));
            rm0 = fmaxf(rm0, __shfl_xor_sync(0xffffffffu, rm0, 2));
            rm1 = fmaxf(rm1, __shfl_xor_sync(0xffffffffu, rm1, 1));
            rm1 = fmaxf(rm1, __shfl_xor_sync(0xffffffffu, rm1, 2));

            float mn0 = fmaxf(mi[b2][0], rm0), mn1 = fmaxf(mi[b2][1], rm1);
            float cr0 = ex2f(mi[b2][0] - mn0), cr1 = ex2f(mi[b2][1] - mn1);
            float rs0 = 0.f, rs1 = 0.f;
#pragma unroll
            for (int n = 0; n < 8; n++) {
                s[b2][n][0] = ex2f(s[b2][n][0] - mn0);
                s[b2][n][1] = ex2f(s[b2][n][1] - mn0);
                s[b2][n][2] = ex2f(s[b2][n][2] - mn1);
                s[b2][n][3] = ex2f(s[b2][n][3] - mn1);
                rs0 += s[b2][n][0] + s[b2][n][1];
                rs1 += s[b2][n][2] + s[b2][n][3];
            }
            rs0 += __shfl_xor_sync(0xffffffffu, rs0, 1);
            rs0 += __shfl_xor_sync(0xffffffffu, rs0, 2);
            rs1 += __shfl_xor_sync(0xffffffffu, rs1, 1);
            rs1 += __shfl_xor_sync(0xffffffffu, rs1, 2);
            li[b2][0] = li[b2][0] * cr0 + rs0;
            li[b2][1] = li[b2][1] * cr1 + rs1;
            mi[b2][0] = mn0; mi[b2][1] = mn1;
#pragma unroll
            for (int nd = 0; nd < 8; nd++) {
                o[b2][nd][0] *= cr0; o[b2][nd][1] *= cr0;
                o[b2][nd][2] *= cr1; o[b2][nd][3] *= cr1;
            }
        }

#pragma unroll
        for (int kb = 0; kb < 4; kb++) {
            uint32_t a0 = packh2(s[0][2 * kb][0], s[0][2 * kb][1]);
            uint32_t a1 = packh2(s[0][2 * kb][2], s[0][2 * kb][3]);
            uint32_t a2 = packh2(s[0][2 * kb + 1][0], s[0][2 * kb + 1][1]);
            uint32_t a3 = packh2(s[0][2 * kb + 1][2], s[0][2 * kb + 1][3]);
            uint32_t c0 = packh2(s[1][2 * kb][0], s[1][2 * kb][1]);
            uint32_t c1 = packh2(s[1][2 * kb][2], s[1][2 * kb][3]);
            uint32_t c2 = packh2(s[1][2 * kb + 1][0], s[1][2 * kb + 1][1]);
            uint32_t c3 = packh2(s[1][2 * kb + 1][2], s[1][2 * kb + 1][3]);
            uint32_t rowoff = (uint32_t)(kb * 16 * SPVH * 2);
#pragma unroll
            for (int dp = 0; dp < 4; dp++) {
                uint32_t b0, b1, b2v, b3;
                asm volatile(
                    "ldmatrix.sync.aligned.m8n8.x4.trans.shared.b16 "
                    "{%0,%1,%2,%3}, [%4];"
                    : "=r"(b0), "=r"(b1), "=r"(b2v), "=r"(b3)
                    : "r"(vb + rowoff + dp * 32));
                mma_f16(o[0][2 * dp], a0, a1, a2, a3, b0, b1);
                mma_f16(o[0][2 * dp + 1], a0, a1, a2, a3, b2v, b3);
                mma_f16(o[1][2 * dp], c0, c1, c2, c3, b0, b1);
                mma_f16(o[1][2 * dp + 1], c0, c1, c2, c3, b2v, b3);
            }
        }
    }

#pragma unroll
    for (int b2 = 0; b2 < 2; b2++) {
        int r0 = qt * 128 + wr + 16 * b2 + g;
        int r1 = r0 + 8;
        float sc0 = qmask[(size_t)b_ * Ss + r0] / li[b2][0];
        float sc1 = qmask[(size_t)b_ * Ss + r1] / li[b2][1];
        float* ob0 = out + ((size_t)b_ * Ss + r0) * DM + h * 64;
        float* ob1 = out + ((size_t)b_ * Ss + r1) * DM + h * 64;
#pragma unroll
        for (int nd = 0; nd < 8; nd++) {
            *(float2*)&ob0[nd * 8 + 2 * t] =
                make_float2(o[b2][nd][0] * sc0, o[b2][nd][1] * sc0);
            *(float2*)&ob1[nd * 8 + 2 * t] =
                make_float2(o[b2][nd][2] * sc1, o[b2][nd][3] * sc1);
        }
    }
}

// Trailing no-op: shifts the ncu -s5-c1 capture window onto proj next round.
__global__ void nop_kernel() {}

extern "C" void kernel_launch(void* const* d_in, const int* in_sizes, int n_in,
                              void* d_out, int out_size)
{
    const float* q     = (const float*)d_in[0];
    const float* k     = (const float*)d_in[1];
    const float* v     = (const float*)d_in[2];
    const float* vmask = (const float*)d_in[3];
    const float* qmask = (const float*)d_in[4];
    const float* Wq    = (const float*)d_in[5];
    const float* Wk    = (const float*)d_in[6];
    const float* Wv    = (const float*)d_in[7];
    float* out = (float*)d_out;

    dim3 cg(9216, 3);
    cvt16_kernel<<<cg, 256>>>(q, k, v, Wq, Wk, Wv);

    cudaFuncSetAttribute(proj_h_kernel,
                         cudaFuncAttributeMaxDynamicSharedMemorySize,
                         PROJ_SMEM_BYTES);
    dim3 pg(DM / 128, (Bb * Ss) / 128, 3);
    proj_h_kernel<<<pg, 256, PROJ_SMEM_BYTES>>>();

    int fa_smem = FA_SMEM_FLOATS * sizeof(float);
    cudaFuncSetAttribute(fa_mma_kernel,
                         cudaFuncAttributeMaxDynamicSharedMemorySize, fa_smem);
    dim3 fg(Ss / 128, Bb * Hh);
    fa_mma_kernel<<<fg, 128, fa_smem>>>(vmask, qmask, out);

    nop_kernel<<<1, 32>>>();
}